// round 1
// baseline (speedup 1.0000x reference)
#include <cuda_runtime.h>
#include <cuda_bf16.h>
#include <math.h>

// ---------------------------------------------------------------------------
// Problem constants
//   B=64, RES=32, DIM=384, NH=8, RD=2
//   x: [64, 32, 32, 384] f32
//   out = DynaMixerBlock(x) : [64, 32, 32, 384] f32
// ---------------------------------------------------------------------------

#define NTOK   25165824   // 64*32*32*384 elements
#define NROWS  65536      // 64*32*32
#define CDIM   384

// Scratch (device globals; allocation-free per harness rules)
__device__ float g_mid[NTOK];   // pre-Wo mixer output (reused for both dirs)
__device__ float g_h[NTOK];
__device__ float g_w[NTOK];
__device__ float g_c[NTOK];     // channel path, then blended sum (in place)
__device__ float g_part[64 * 16 * 384];
__device__ float g_a[3 * 64 * 384];

// ---------------------------------------------------------------------------
// Fused DynaMixer mixing (per sequence): compress -> generate -> softmax -> mix
// dir=0: mix along H (sequence = (b, w_col), stride 32*384)
// dir=1: mix along W (sequence = (b, h_row), stride 384)
// out gets the pre-Wo mixed tensor already laid out as [B,H,W,C].
// ---------------------------------------------------------------------------
#define SMW(h, l, j) smw[(h) * 1056 + (l) * 33 + (j)]

__global__ __launch_bounds__(256) void mix_kernel(
    const float* __restrict__ x,
    const float* __restrict__ Wc,   // [16, 384]
    const float* __restrict__ bc,   // [16]
    const float* __restrict__ Wg,   // [1024, 64]
    const float* __restrict__ bg,   // [1024]
    float* __restrict__ out,
    int dir)
{
    __shared__ float smw[8 * 1056];   // [8][32][33] padded softmax weights
    __shared__ float vs[8 * 64];      // compressed vectors per head

    const int n = blockIdx.x;          // 0..2047
    const int b = n >> 5;
    const int q = n & 31;
    long base;
    int stride;
    if (dir == 0) { base = ((long)b * 1024 + q) * 384; stride = 32 * 384; }
    else          { base = ((long)(b * 32 + q)) * 32 * 384; stride = 384; }

    const int tid = threadIdx.x;       // 256 threads

    // --- phase 1: compress  wcomp[l][o] = x[l,:] . Wc[o,:] + bc[o] ---
    for (int idx = tid; idx < 512; idx += 256) {
        const int l = idx >> 4;
        const int o = idx & 15;
        const float4* xr = (const float4*)&x[base + (long)l * stride];
        const float4* wr = (const float4*)&Wc[o * 384];
        float s = bc[o];
#pragma unroll 8
        for (int c4 = 0; c4 < 96; c4++) {
            float4 xv = xr[c4];
            float4 wv = wr[c4];
            s += xv.x * wv.x + xv.y * wv.y + xv.z * wv.z + xv.w * wv.w;
        }
        // v[h][l*2+r], h = o/2, r = o%2
        vs[(o >> 1) * 64 + l * 2 + (o & 1)] = s;
    }
    __syncthreads();

    // --- phase 2: generate  w2[h][m] = vs[h,:] . Wg[m,:] + bg[m] ---
    for (int idx = tid; idx < 8192; idx += 256) {
        const int h = idx >> 10;
        const int m = idx & 1023;
        const float4* wr = (const float4*)&Wg[m * 64];
        const float4* vv = (const float4*)&vs[h * 64];
        float s = bg[m];
#pragma unroll
        for (int k4 = 0; k4 < 16; k4++) {
            float4 wv = wr[k4];
            float4 v = vv[k4];
            s += wv.x * v.x + wv.y * v.y + wv.z * v.z + wv.w * v.w;
        }
        SMW(h, m >> 5, m & 31) = s;
    }
    __syncthreads();

    // --- phase 3: softmax over l (rows) for each (h, j) ---
    {
        const int h = tid >> 5;
        const int j = tid & 31;
        float mx = -1e30f;
#pragma unroll
        for (int l = 0; l < 32; l++) mx = fmaxf(mx, SMW(h, l, j));
        float sum = 0.f;
#pragma unroll
        for (int l = 0; l < 32; l++) {
            float e = __expf(SMW(h, l, j) - mx);
            SMW(h, l, j) = e;
            sum += e;
        }
        float inv = 1.f / sum;
#pragma unroll
        for (int l = 0; l < 32; l++) SMW(h, l, j) *= inv;
    }
    __syncthreads();

    // --- phase 4: mix  y[j][c] = sum_l x[l][c] * smw[c/48][l][j] ---
    for (int idx = tid; idx < 12288; idx += 256) {
        const int j = idx / 384;
        const int c = idx - j * 384;
        const int h = c / 48;
        float s = 0.f;
#pragma unroll
        for (int l = 0; l < 32; l++)
            s += x[base + (long)l * stride + c] * SMW(h, l, j);
        out[base + (long)j * stride + c] = s;
    }
}

// ---------------------------------------------------------------------------
// SGEMM (NT): C[M,N] = A[M,K] * W[N,K]^T (+ bias[N])
// Fixed assumptions: M%128==0, N%128==0, K%16==0, K%4==0, 16B-aligned ptrs.
// 128x128 tile, BK=16, 256 threads, 8x8 per thread.
// ---------------------------------------------------------------------------
__global__ __launch_bounds__(256) void sgemm_nt_kernel(
    const float* __restrict__ A,
    const float* __restrict__ W,
    const float* __restrict__ bias,   // may be null
    float* __restrict__ C,
    int M, int N, int K)
{
    __shared__ float As[16][128];
    __shared__ float Ws[16][128];

    const int tid = threadIdx.x;
    const int tx = tid & 15;
    const int ty = tid >> 4;
    const int rowBase = blockIdx.y * 128;
    const int colBase = blockIdx.x * 128;

    float acc[8][8] = {};

    for (int kt = 0; kt < K; kt += 16) {
#pragma unroll
        for (int s = 0; s < 2; s++) {
            const int id = tid + s * 256;         // 0..511
            const int r = id >> 2;                // tile row 0..127
            const int k4 = (id & 3) * 4;          // k offset 0,4,8,12
            float4 va = *(const float4*)&A[(long)(rowBase + r) * K + kt + k4];
            As[k4 + 0][r] = va.x;
            As[k4 + 1][r] = va.y;
            As[k4 + 2][r] = va.z;
            As[k4 + 3][r] = va.w;
            float4 vw = *(const float4*)&W[(long)(colBase + r) * K + kt + k4];
            Ws[k4 + 0][r] = vw.x;
            Ws[k4 + 1][r] = vw.y;
            Ws[k4 + 2][r] = vw.z;
            Ws[k4 + 3][r] = vw.w;
        }
        __syncthreads();

#pragma unroll
        for (int k = 0; k < 16; k++) {
            float a[8], bb[8];
            *(float4*)&a[0]  = *(const float4*)&As[k][ty * 8];
            *(float4*)&a[4]  = *(const float4*)&As[k][ty * 8 + 4];
            *(float4*)&bb[0] = *(const float4*)&Ws[k][tx * 8];
            *(float4*)&bb[4] = *(const float4*)&Ws[k][tx * 8 + 4];
#pragma unroll
            for (int i = 0; i < 8; i++)
#pragma unroll
                for (int j = 0; j < 8; j++)
                    acc[i][j] += a[i] * bb[j];
        }
        __syncthreads();
    }

#pragma unroll
    for (int i = 0; i < 8; i++) {
        const long row = rowBase + ty * 8 + i;
#pragma unroll
        for (int j = 0; j < 8; j += 4) {
            const int col = colBase + tx * 8 + j;
            float4 v;
            v.x = acc[i][j];
            v.y = acc[i][j + 1];
            v.z = acc[i][j + 2];
            v.w = acc[i][j + 3];
            if (bias) {
                v.x += bias[col];
                v.y += bias[col + 1];
                v.z += bias[col + 2];
                v.w += bias[col + 3];
            }
            *(float4*)&C[row * N + col] = v;
        }
    }
}

// ---------------------------------------------------------------------------
// Pool stage 1: partial sums of (h + w + c) over 64 positions each.
// grid (64, 16), 384 threads.
// ---------------------------------------------------------------------------
__global__ __launch_bounds__(384) void pool1_kernel(
    const float* __restrict__ h,
    const float* __restrict__ w,
    const float* __restrict__ c,
    float* __restrict__ part)
{
    const int b = blockIdx.x;
    const int ch = blockIdx.y;
    const int t = threadIdx.x;
    long base = ((long)b * 1024 + ch * 64) * 384 + t;
    float s = 0.f;
#pragma unroll 8
    for (int p = 0; p < 64; p++) {
        long o = base + (long)p * 384;
        s += h[o] + w[o] + c[o];
    }
    part[(b * 16 + ch) * 384 + t] = s;
}

// ---------------------------------------------------------------------------
// Reweighting MLP + 3-way softmax. One block per batch element.
// ---------------------------------------------------------------------------
__global__ __launch_bounds__(384) void mlp_kernel(
    const float* __restrict__ part,
    const float* __restrict__ Wr1, const float* __restrict__ br1,   // [96,384],[96]
    const float* __restrict__ Wr2, const float* __restrict__ br2,   // [1152,96],[1152]
    float* __restrict__ ga)                                          // [3,64,384]
{
    __shared__ float pool_s[384];
    __shared__ float a1_s[96];
    const int b = blockIdx.x;
    const int t = threadIdx.x;

    float s = 0.f;
#pragma unroll
    for (int ch = 0; ch < 16; ch++) s += part[(b * 16 + ch) * 384 + t];
    pool_s[t] = s * (1.f / 1024.f);
    __syncthreads();

    if (t < 96) {
        float acc = br1[t];
        const float* wr = &Wr1[t * 384];
#pragma unroll 8
        for (int c = 0; c < 384; c++) acc += pool_s[c] * wr[c];
        // exact GELU: 0.5*x*(1+erf(x/sqrt(2)))
        a1_s[t] = 0.5f * acc * (1.f + erff(acc * 0.70710678118654752f));
    }
    __syncthreads();

    float v[3];
#pragma unroll
    for (int k = 0; k < 3; k++) {
        const int o = t * 3 + k;
        float acc = br2[o];
        const float* wr = &Wr2[o * 96];
#pragma unroll 8
        for (int i = 0; i < 96; i++) acc += a1_s[i] * wr[i];
        v[k] = acc;
    }
    float mx = fmaxf(v[0], fmaxf(v[1], v[2]));
    float e0 = __expf(v[0] - mx);
    float e1 = __expf(v[1] - mx);
    float e2 = __expf(v[2] - mx);
    float inv = 1.f / (e0 + e1 + e2);
    ga[(0 * 64 + b) * 384 + t] = e0 * inv;
    ga[(1 * 64 + b) * 384 + t] = e1 * inv;
    ga[(2 * 64 + b) * 384 + t] = e2 * inv;
}

// ---------------------------------------------------------------------------
// Blend: c[e] = h[e]*a0[b,c] + w[e]*a1[b,c] + c[e]*a2[b,c]   (in place into c)
// ---------------------------------------------------------------------------
__global__ __launch_bounds__(256) void blend_kernel(
    const float* __restrict__ h,
    const float* __restrict__ w,
    float* __restrict__ c,
    const float* __restrict__ ga)
{
    const long i4 = (long)blockIdx.x * blockDim.x + threadIdx.x;
    if (i4 >= (NTOK / 4)) return;
    const long e = i4 * 4;
    const int b = (int)(e / (1024 * 384));
    const int ci = (int)(e % 384);

    float4 h4 = *(const float4*)&h[e];
    float4 w4 = *(const float4*)&w[e];
    float4 c4 = *(const float4*)&c[e];
    float4 a0 = *(const float4*)&ga[(0 * 64 + b) * 384 + ci];
    float4 a1 = *(const float4*)&ga[(1 * 64 + b) * 384 + ci];
    float4 a2 = *(const float4*)&ga[(2 * 64 + b) * 384 + ci];
    float4 r;
    r.x = h4.x * a0.x + w4.x * a1.x + c4.x * a2.x;
    r.y = h4.y * a0.y + w4.y * a1.y + c4.y * a2.y;
    r.z = h4.z * a0.z + w4.z * a1.z + c4.z * a2.z;
    r.w = h4.w * a0.w + w4.w * a1.w + c4.w * a2.w;
    *(float4*)&c[e] = r;
}

// ---------------------------------------------------------------------------
// Launch
// ---------------------------------------------------------------------------
extern "C" void kernel_launch(void* const* d_in, const int* in_sizes, int n_in,
                              void* d_out, int out_size)
{
    const float* x     = (const float*)d_in[0];
    const float* Wc_h  = (const float*)d_in[1];
    const float* bc_h  = (const float*)d_in[2];
    const float* Wg_h  = (const float*)d_in[3];
    const float* bg_h  = (const float*)d_in[4];
    const float* Wo_h  = (const float*)d_in[5];
    const float* bo_h  = (const float*)d_in[6];
    const float* Wc_w  = (const float*)d_in[7];
    const float* bc_w  = (const float*)d_in[8];
    const float* Wg_w  = (const float*)d_in[9];
    const float* bg_w  = (const float*)d_in[10];
    const float* Wo_w  = (const float*)d_in[11];
    const float* bo_w  = (const float*)d_in[12];
    const float* Wmlpc = (const float*)d_in[13];
    const float* Wr1   = (const float*)d_in[14];
    const float* br1   = (const float*)d_in[15];
    const float* Wr2   = (const float*)d_in[16];
    const float* br2   = (const float*)d_in[17];
    const float* Wp    = (const float*)d_in[18];
    const float* bp    = (const float*)d_in[19];
    float* out = (float*)d_out;

    float *p_mid, *p_h, *p_w, *p_c, *p_part, *p_a;
    cudaGetSymbolAddress((void**)&p_mid,  g_mid);
    cudaGetSymbolAddress((void**)&p_h,    g_h);
    cudaGetSymbolAddress((void**)&p_w,    g_w);
    cudaGetSymbolAddress((void**)&p_c,    g_c);
    cudaGetSymbolAddress((void**)&p_part, g_part);
    cudaGetSymbolAddress((void**)&p_a,    g_a);

    dim3 ggemm(CDIM / 128, NROWS / 128);   // (3, 512)

    // H-direction mix + Wo_h projection
    mix_kernel<<<2048, 256>>>(x, Wc_h, bc_h, Wg_h, bg_h, p_mid, 0);
    sgemm_nt_kernel<<<ggemm, 256>>>(p_mid, Wo_h, bo_h, p_h, NROWS, CDIM, CDIM);

    // W-direction mix + Wo_w projection
    mix_kernel<<<2048, 256>>>(x, Wc_w, bc_w, Wg_w, bg_w, p_mid, 1);
    sgemm_nt_kernel<<<ggemm, 256>>>(p_mid, Wo_w, bo_w, p_w, NROWS, CDIM, CDIM);

    // channel path (no bias)
    sgemm_nt_kernel<<<ggemm, 256>>>(x, Wmlpc, nullptr, p_c, NROWS, CDIM, CDIM);

    // global pool + reweighting MLP + 3-way softmax
    pool1_kernel<<<dim3(64, 16), 384>>>(p_h, p_w, p_c, p_part);
    mlp_kernel<<<64, 384>>>(p_part, Wr1, br1, Wr2, br2, p_a);

    // blend into p_c in place
    blend_kernel<<<(NTOK / 4 + 255) / 256, 256>>>(p_h, p_w, p_c, p_a);

    // final projection
    sgemm_nt_kernel<<<ggemm, 256>>>(p_c, Wp, bp, out, NROWS, CDIM, CDIM);
}

// round 3
// speedup vs baseline: 2.0407x; 2.0407x over previous
#include <cuda_runtime.h>
#include <cuda_bf16.h>
#include <math.h>
#include <stdint.h>

// ---------------------------------------------------------------------------
// Problem constants: B=64, RES=32, DIM=384, NH=8, RD=2
// x: [64,32,32,384] f32 ; out: same shape
// ---------------------------------------------------------------------------
#define NTOK   25165824   // 64*32*32*384
#define NROWS  65536
#define CDIM   384

// Scratch (device globals; allocation-free)
__device__ float g_mid[NTOK];
__device__ float g_h[NTOK];
__device__ float g_w[NTOK];
__device__ float g_c[NTOK];
__device__ float g_part[64 * 16 * 384];
__device__ float g_a[3 * 64 * 384];

__device__ __forceinline__ float tf32_rna(float x) {
    uint32_t u;
    asm("cvt.rna.tf32.f32 %0, %1;" : "=r"(u) : "f"(x));
    return __uint_as_float(u);
}

__device__ __forceinline__ void mma_tf32(float* d, const uint32_t* a, const uint32_t* b) {
    asm volatile(
        "mma.sync.aligned.m16n8k8.row.col.f32.tf32.tf32.f32 "
        "{%0,%1,%2,%3}, {%4,%5,%6,%7}, {%8,%9}, {%0,%1,%2,%3};"
        : "+f"(d[0]), "+f"(d[1]), "+f"(d[2]), "+f"(d[3])
        : "r"(a[0]), "r"(a[1]), "r"(a[2]), "r"(a[3]), "r"(b[0]), "r"(b[1]));
}

// ===========================================================================
// Tensor-core tf32 GEMM (NT): C[M,384] = A[M,384] * W[384,384]^T (+bias)
// Block tile 128x128, BK=32, 256 threads / 8 warps (2x4), warp tile 64x32.
// smem row stride 36 floats -> conflict-free fragment loads.
// Grid (3, M/128).
// ===========================================================================
#define ASTRIDE 36

__global__ __launch_bounds__(256, 2) void gemm_mma_kernel(
    const float* __restrict__ A,
    const float* __restrict__ W,
    const float* __restrict__ bias,   // may be null
    float* __restrict__ C)
{
    __shared__ float As[128 * ASTRIDE];
    __shared__ float Ws[128 * ASTRIDE];

    const int tid  = threadIdx.x;
    const int lane = tid & 31;
    const int wid  = tid >> 5;
    const int gID  = lane >> 2;    // 0..7
    const int tig  = lane & 3;     // 0..3
    const int wm   = (wid >> 2) * 64;   // warp m offset (0,64)
    const int wn   = (wid & 3) * 32;    // warp n offset (0,32,64,96)

    const long rowBase = (long)blockIdx.y * 128;
    const int  colBase = blockIdx.x * 128;
    const float* Abase = A + rowBase * 384;
    const float* Wbase = W + (long)colBase * 384;

    float acc[4][4][4];
#pragma unroll
    for (int i = 0; i < 4; i++)
#pragma unroll
        for (int j = 0; j < 4; j++)
#pragma unroll
            for (int r = 0; r < 4; r++) acc[i][j][r] = 0.f;

#pragma unroll 1
    for (int kt = 0; kt < 384; kt += 32) {
        // load tiles: 128 rows x 32 cols each, tf32-rounded
#pragma unroll
        for (int s = 0; s < 4; s++) {
            const int idx = tid + s * 256;      // 0..1023
            const int r = idx >> 3;
            const int g = (idx & 7) * 4;
            float4 va = *(const float4*)(Abase + (long)r * 384 + kt + g);
            va.x = tf32_rna(va.x); va.y = tf32_rna(va.y);
            va.z = tf32_rna(va.z); va.w = tf32_rna(va.w);
            float* pa = &As[r * ASTRIDE + g];
            *(float2*)(pa)     = make_float2(va.x, va.y);
            *(float2*)(pa + 2) = make_float2(va.z, va.w);
            float4 vw = *(const float4*)(Wbase + (long)r * 384 + kt + g);
            vw.x = tf32_rna(vw.x); vw.y = tf32_rna(vw.y);
            vw.z = tf32_rna(vw.z); vw.w = tf32_rna(vw.w);
            float* pw = &Ws[r * ASTRIDE + g];
            *(float2*)(pw)     = make_float2(vw.x, vw.y);
            *(float2*)(pw + 2) = make_float2(vw.z, vw.w);
        }
        __syncthreads();

#pragma unroll
        for (int kk = 0; kk < 32; kk += 8) {
            uint32_t af[4][4], bf[4][2];
#pragma unroll
            for (int mt = 0; mt < 4; mt++) {
                const int row0 = wm + mt * 16 + gID;
                af[mt][0] = __float_as_uint(As[row0 * ASTRIDE + kk + tig]);
                af[mt][1] = __float_as_uint(As[(row0 + 8) * ASTRIDE + kk + tig]);
                af[mt][2] = __float_as_uint(As[row0 * ASTRIDE + kk + tig + 4]);
                af[mt][3] = __float_as_uint(As[(row0 + 8) * ASTRIDE + kk + tig + 4]);
            }
#pragma unroll
            for (int nt = 0; nt < 4; nt++) {
                const int col0 = wn + nt * 8 + gID;
                bf[nt][0] = __float_as_uint(Ws[col0 * ASTRIDE + kk + tig]);
                bf[nt][1] = __float_as_uint(Ws[col0 * ASTRIDE + kk + tig + 4]);
            }
#pragma unroll
            for (int mt = 0; mt < 4; mt++)
#pragma unroll
                for (int nt = 0; nt < 4; nt++)
                    mma_tf32(acc[mt][nt], af[mt], bf[nt]);
        }
        __syncthreads();
    }

    // epilogue
#pragma unroll
    for (int mt = 0; mt < 4; mt++) {
        const long row0 = rowBase + wm + mt * 16 + gID;
#pragma unroll
        for (int nt = 0; nt < 4; nt++) {
            const int col = colBase + wn + nt * 8 + tig * 2;
            float bx = 0.f, by = 0.f;
            if (bias) { bx = bias[col]; by = bias[col + 1]; }
            *(float2*)(C + row0 * 384 + col) =
                make_float2(acc[mt][nt][0] + bx, acc[mt][nt][1] + by);
            *(float2*)(C + (row0 + 8) * 384 + col) =
                make_float2(acc[mt][nt][2] + bx, acc[mt][nt][3] + by);
        }
    }
}

// ===========================================================================
// Fused DynaMixer mixing (per sequence): compress -> generate -> softmax -> mix
// Dynamic smem: xs[32*384] | smw[8*1056] | vs[8*68] | wgs[32*65]
// ===========================================================================
#define MIX_SMEM_FLOATS (12288 + 8448 + 544 + 2080)
#define MIX_SMEM_BYTES (MIX_SMEM_FLOATS * 4)

__global__ __launch_bounds__(256) void mix_kernel(
    const float* __restrict__ x,
    const float* __restrict__ Wc,   // [16, 384]
    const float* __restrict__ bc,   // [16]
    const float* __restrict__ Wg,   // [1024, 64]
    const float* __restrict__ bg,   // [1024]
    float* __restrict__ out,
    int dir)
{
    extern __shared__ float sm[];
    float* xs  = sm;                 // [32][384]
    float* smw = sm + 12288;         // [8][32][33]
    float* vs  = sm + 12288 + 8448;  // [8][68]
    float* wgs = vs + 544;           // [32][65]
#define SMW(h, l, j) smw[(h) * 1056 + (l) * 33 + (j)]

    const int n = blockIdx.x;
    const int b = n >> 5;
    const int q = n & 31;
    long base;
    int stride;
    if (dir == 0) { base = ((long)b * 1024 + q) * 384; stride = 32 * 384; }
    else          { base = ((long)(b * 32 + q)) * 32 * 384; stride = 384; }

    const int tid = threadIdx.x;

    // --- stage x sequence into smem: 32 rows x 384 ---
    for (int i = tid; i < 3072; i += 256) {
        const int r = i / 96;
        const int c4 = i - r * 96;
        *(float4*)&xs[r * 384 + c4 * 4] =
            *(const float4*)&x[base + (long)r * stride + c4 * 4];
    }
    __syncthreads();

    // --- phase 1: compress  vs[h][l*2+r] = xs[l,:] . Wc[o,:] + bc[o] ---
    for (int idx = tid; idx < 512; idx += 256) {
        const int l = idx >> 4;
        const int o = idx & 15;
        const float4* xr = (const float4*)&xs[l * 384];
        const float4* wr = (const float4*)&Wc[o * 384];
        float s = bc[o];
#pragma unroll 8
        for (int c4 = 0; c4 < 96; c4++) {
            float4 xv = xr[c4];
            float4 wv = wr[c4];
            s += xv.x * wv.x + xv.y * wv.y + xv.z * wv.z + xv.w * wv.w;
        }
        vs[(o >> 1) * 68 + l * 2 + (o & 1)] = s;
    }
    __syncthreads();

    // --- phase 2: generate (smem-staged Wg) ---
    {
        const int ml = tid >> 3;   // 0..31
        const int h  = tid & 7;
        const float* vr = &vs[h * 68];
        for (int t0 = 0; t0 < 1024; t0 += 32) {
            for (int i = tid; i < 512; i += 256) {
                const int r = i >> 4;
                const int g = i & 15;
                float4 v = *(const float4*)&Wg[(t0 + r) * 64 + g * 4];
                wgs[r * 65 + g * 4 + 0] = v.x;
                wgs[r * 65 + g * 4 + 1] = v.y;
                wgs[r * 65 + g * 4 + 2] = v.z;
                wgs[r * 65 + g * 4 + 3] = v.w;
            }
            __syncthreads();
            const int m = t0 + ml;
            float s = bg[m];
            const float* wr = &wgs[ml * 65];
#pragma unroll 16
            for (int k = 0; k < 64; k++) s += vr[k] * wr[k];
            SMW(h, m >> 5, m & 31) = s;
            __syncthreads();
        }
    }

    // --- phase 3: softmax over rows l for each (h, j) ---
    {
        const int h = tid >> 5;
        const int j = tid & 31;
        float mx = -1e30f;
#pragma unroll
        for (int l = 0; l < 32; l++) mx = fmaxf(mx, SMW(h, l, j));
        float sum = 0.f;
#pragma unroll
        for (int l = 0; l < 32; l++) {
            float e = __expf(SMW(h, l, j) - mx);
            SMW(h, l, j) = e;
            sum += e;
        }
        float inv = 1.f / sum;
#pragma unroll
        for (int l = 0; l < 32; l++) SMW(h, l, j) *= inv;
    }
    __syncthreads();

    // --- phase 4: mix  y[j][c] = sum_l xs[l][c] * smw[c/48][l][j] ---
    for (int idx = tid; idx < 3072; idx += 256) {
        const int j  = idx / 96;
        const int c4 = idx - j * 96;
        const int h  = c4 / 12;
        float4 a = make_float4(0.f, 0.f, 0.f, 0.f);
#pragma unroll
        for (int l = 0; l < 32; l++) {
            const float w = SMW(h, l, j);
            const float4 xv = *(const float4*)&xs[l * 384 + c4 * 4];
            a.x += xv.x * w; a.y += xv.y * w;
            a.z += xv.z * w; a.w += xv.w * w;
        }
        *(float4*)&out[base + (long)j * stride + c4 * 4] = a;
    }
#undef SMW
}

// ===========================================================================
// Pool stage 1: partial sums of (h + w + c)
// ===========================================================================
__global__ __launch_bounds__(384) void pool1_kernel(
    const float* __restrict__ h,
    const float* __restrict__ w,
    const float* __restrict__ c,
    float* __restrict__ part)
{
    const int b = blockIdx.x;
    const int ch = blockIdx.y;
    const int t = threadIdx.x;
    long base = ((long)b * 1024 + ch * 64) * 384 + t;
    float s = 0.f;
#pragma unroll 8
    for (int p = 0; p < 64; p++) {
        long o = base + (long)p * 384;
        s += h[o] + w[o] + c[o];
    }
    part[(b * 16 + ch) * 384 + t] = s;
}

// ===========================================================================
// Reweighting MLP + 3-way softmax
// ===========================================================================
__global__ __launch_bounds__(384) void mlp_kernel(
    const float* __restrict__ part,
    const float* __restrict__ Wr1, const float* __restrict__ br1,
    const float* __restrict__ Wr2, const float* __restrict__ br2,
    float* __restrict__ ga)
{
    __shared__ float pool_s[384];
    __shared__ float a1_s[96];
    const int b = blockIdx.x;
    const int t = threadIdx.x;

    float s = 0.f;
#pragma unroll
    for (int ch = 0; ch < 16; ch++) s += part[(b * 16 + ch) * 384 + t];
    pool_s[t] = s * (1.f / 1024.f);
    __syncthreads();

    if (t < 96) {
        float acc = br1[t];
        const float* wr = &Wr1[t * 384];
#pragma unroll 8
        for (int c = 0; c < 384; c++) acc += pool_s[c] * wr[c];
        a1_s[t] = 0.5f * acc * (1.f + erff(acc * 0.70710678118654752f));
    }
    __syncthreads();

    float v[3];
#pragma unroll
    for (int k = 0; k < 3; k++) {
        const int o = t * 3 + k;
        float acc = br2[o];
        const float* wr = &Wr2[o * 96];
#pragma unroll 8
        for (int i = 0; i < 96; i++) acc += a1_s[i] * wr[i];
        v[k] = acc;
    }
    float mx = fmaxf(v[0], fmaxf(v[1], v[2]));
    float e0 = __expf(v[0] - mx);
    float e1 = __expf(v[1] - mx);
    float e2 = __expf(v[2] - mx);
    float inv = 1.f / (e0 + e1 + e2);
    ga[(0 * 64 + b) * 384 + t] = e0 * inv;
    ga[(1 * 64 + b) * 384 + t] = e1 * inv;
    ga[(2 * 64 + b) * 384 + t] = e2 * inv;
}

// ===========================================================================
// Blend (in place into c)
// ===========================================================================
__global__ __launch_bounds__(256) void blend_kernel(
    const float* __restrict__ h,
    const float* __restrict__ w,
    float* __restrict__ c,
    const float* __restrict__ ga)
{
    const long i4 = (long)blockIdx.x * blockDim.x + threadIdx.x;
    if (i4 >= (NTOK / 4)) return;
    const long e = i4 * 4;
    const int b = (int)(e / (1024 * 384));
    const int ci = (int)(e % 384);

    float4 h4 = *(const float4*)&h[e];
    float4 w4 = *(const float4*)&w[e];
    float4 c4 = *(const float4*)&c[e];
    float4 a0 = *(const float4*)&ga[(0 * 64 + b) * 384 + ci];
    float4 a1 = *(const float4*)&ga[(1 * 64 + b) * 384 + ci];
    float4 a2 = *(const float4*)&ga[(2 * 64 + b) * 384 + ci];
    float4 r;
    r.x = h4.x * a0.x + w4.x * a1.x + c4.x * a2.x;
    r.y = h4.y * a0.y + w4.y * a1.y + c4.y * a2.y;
    r.z = h4.z * a0.z + w4.z * a1.z + c4.z * a2.z;
    r.w = h4.w * a0.w + w4.w * a1.w + c4.w * a2.w;
    *(float4*)&c[e] = r;
}

// ===========================================================================
// Launch
// ===========================================================================
extern "C" void kernel_launch(void* const* d_in, const int* in_sizes, int n_in,
                              void* d_out, int out_size)
{
    const float* x     = (const float*)d_in[0];
    const float* Wc_h  = (const float*)d_in[1];
    const float* bc_h  = (const float*)d_in[2];
    const float* Wg_h  = (const float*)d_in[3];
    const float* bg_h  = (const float*)d_in[4];
    const float* Wo_h  = (const float*)d_in[5];
    const float* bo_h  = (const float*)d_in[6];
    const float* Wc_w  = (const float*)d_in[7];
    const float* bc_w  = (const float*)d_in[8];
    const float* Wg_w  = (const float*)d_in[9];
    const float* bg_w  = (const float*)d_in[10];
    const float* Wo_w  = (const float*)d_in[11];
    const float* bo_w  = (const float*)d_in[12];
    const float* Wmlpc = (const float*)d_in[13];
    const float* Wr1   = (const float*)d_in[14];
    const float* br1   = (const float*)d_in[15];
    const float* Wr2   = (const float*)d_in[16];
    const float* br2   = (const float*)d_in[17];
    const float* Wp    = (const float*)d_in[18];
    const float* bp    = (const float*)d_in[19];
    float* out = (float*)d_out;

    float *p_mid, *p_h, *p_w, *p_c, *p_part, *p_a;
    cudaGetSymbolAddress((void**)&p_mid,  g_mid);
    cudaGetSymbolAddress((void**)&p_h,    g_h);
    cudaGetSymbolAddress((void**)&p_w,    g_w);
    cudaGetSymbolAddress((void**)&p_c,    g_c);
    cudaGetSymbolAddress((void**)&p_part, g_part);
    cudaGetSymbolAddress((void**)&p_a,    g_a);

    cudaFuncSetAttribute(mix_kernel,
                         cudaFuncAttributeMaxDynamicSharedMemorySize,
                         MIX_SMEM_BYTES);

    dim3 ggemm(3, NROWS / 128);   // (3, 512)

    // H-direction mix + Wo_h projection
    mix_kernel<<<2048, 256, MIX_SMEM_BYTES>>>(x, Wc_h, bc_h, Wg_h, bg_h, p_mid, 0);
    gemm_mma_kernel<<<ggemm, 256>>>(p_mid, Wo_h, bo_h, p_h);

    // W-direction mix + Wo_w projection
    mix_kernel<<<2048, 256, MIX_SMEM_BYTES>>>(x, Wc_w, bc_w, Wg_w, bg_w, p_mid, 1);
    gemm_mma_kernel<<<ggemm, 256>>>(p_mid, Wo_w, bo_w, p_w);

    // channel path (no bias)
    gemm_mma_kernel<<<ggemm, 256>>>(x, Wmlpc, nullptr, p_c);

    // pool + reweighting MLP
    pool1_kernel<<<dim3(64, 16), 384>>>(p_h, p_w, p_c, p_part);
    mlp_kernel<<<64, 384>>>(p_part, Wr1, br1, Wr2, br2, p_a);

    // blend into p_c
    blend_kernel<<<(NTOK / 4 + 255) / 256, 256>>>(p_h, p_w, p_c, p_a);

    // final projection
    gemm_mma_kernel<<<ggemm, 256>>>(p_c, Wp, bp, out);
}

// round 4
// speedup vs baseline: 2.4808x; 1.2157x over previous
#include <cuda_runtime.h>
#include <cuda_bf16.h>
#include <math.h>
#include <stdint.h>

// ---------------------------------------------------------------------------
// Problem constants: B=64, RES=32, DIM=384, NH=8, RD=2
// ---------------------------------------------------------------------------
#define NTOK   25165824   // 64*32*32*384
#define NROWS  65536
#define CDIM   384

// Scratch (device globals; allocation-free)
__device__ float g_mid[NTOK];
__device__ float g_h[NTOK];
__device__ float g_w[NTOK];
__device__ float g_c[NTOK];
__device__ float g_part[64 * 16 * 384];
__device__ float g_a[3 * 64 * 384];
__device__ float g_vh[2048 * 8 * 64];       // compress output, H-mix order
__device__ float g_vw[2048 * 8 * 64];       // compress output, W-mix order
__device__ float g_logits[16384 * 1024];    // 64 MB, reused per direction

__device__ __forceinline__ float tf32_rna(float x) {
    uint32_t u;
    asm("cvt.rna.tf32.f32 %0, %1;" : "=r"(u) : "f"(x));
    return __uint_as_float(u);
}

__device__ __forceinline__ void mma_tf32(float* d, const uint32_t* a, const uint32_t* b) {
    asm volatile(
        "mma.sync.aligned.m16n8k8.row.col.f32.tf32.tf32.f32 "
        "{%0,%1,%2,%3}, {%4,%5,%6,%7}, {%8,%9}, {%0,%1,%2,%3};"
        : "+f"(d[0]), "+f"(d[1]), "+f"(d[2]), "+f"(d[3])
        : "r"(a[0]), "r"(a[1]), "r"(a[2]), "r"(a[3]), "r"(b[0]), "r"(b[1]));
}

// ===========================================================================
// Generic tensor-core tf32 GEMM (NT): C[M,N] = A[M,K] * W[N,K]^T (+bias)
// Block tile 128x128, BK=32, 256 threads / 8 warps (2x4), warp tile 64x32.
// Grid (N/128, M/128). Requires M%128==0, N%128==0, K%32==0.
// ===========================================================================
#define ASTRIDE 36

__global__ __launch_bounds__(256, 2) void gemm_mma_g(
    const float* __restrict__ A, int lda,
    const float* __restrict__ W, int ldw,
    const float* __restrict__ bias,   // may be null
    float* __restrict__ C, int ldc, int K)
{
    __shared__ float As[128 * ASTRIDE];
    __shared__ float Ws[128 * ASTRIDE];

    const int tid  = threadIdx.x;
    const int lane = tid & 31;
    const int wid  = tid >> 5;
    const int gID  = lane >> 2;
    const int tig  = lane & 3;
    const int wm   = (wid >> 2) * 64;
    const int wn   = (wid & 3) * 32;

    const long rowBase = (long)blockIdx.y * 128;
    const int  colBase = blockIdx.x * 128;
    const float* Abase = A + rowBase * lda;
    const float* Wbase = W + (long)colBase * ldw;

    float acc[4][4][4];
#pragma unroll
    for (int i = 0; i < 4; i++)
#pragma unroll
        for (int j = 0; j < 4; j++)
#pragma unroll
            for (int r = 0; r < 4; r++) acc[i][j][r] = 0.f;

#pragma unroll 1
    for (int kt = 0; kt < K; kt += 32) {
#pragma unroll
        for (int s = 0; s < 4; s++) {
            const int idx = tid + s * 256;
            const int r = idx >> 3;
            const int g = (idx & 7) * 4;
            float4 va = *(const float4*)(Abase + (long)r * lda + kt + g);
            va.x = tf32_rna(va.x); va.y = tf32_rna(va.y);
            va.z = tf32_rna(va.z); va.w = tf32_rna(va.w);
            float* pa = &As[r * ASTRIDE + g];
            *(float2*)(pa)     = make_float2(va.x, va.y);
            *(float2*)(pa + 2) = make_float2(va.z, va.w);
            float4 vw = *(const float4*)(Wbase + (long)r * ldw + kt + g);
            vw.x = tf32_rna(vw.x); vw.y = tf32_rna(vw.y);
            vw.z = tf32_rna(vw.z); vw.w = tf32_rna(vw.w);
            float* pw = &Ws[r * ASTRIDE + g];
            *(float2*)(pw)     = make_float2(vw.x, vw.y);
            *(float2*)(pw + 2) = make_float2(vw.z, vw.w);
        }
        __syncthreads();

#pragma unroll
        for (int kk = 0; kk < 32; kk += 8) {
            uint32_t af[4][4], bf[4][2];
#pragma unroll
            for (int mt = 0; mt < 4; mt++) {
                const int row0 = wm + mt * 16 + gID;
                af[mt][0] = __float_as_uint(As[row0 * ASTRIDE + kk + tig]);
                af[mt][1] = __float_as_uint(As[(row0 + 8) * ASTRIDE + kk + tig]);
                af[mt][2] = __float_as_uint(As[row0 * ASTRIDE + kk + tig + 4]);
                af[mt][3] = __float_as_uint(As[(row0 + 8) * ASTRIDE + kk + tig + 4]);
            }
#pragma unroll
            for (int nt = 0; nt < 4; nt++) {
                const int col0 = wn + nt * 8 + gID;
                bf[nt][0] = __float_as_uint(Ws[col0 * ASTRIDE + kk + tig]);
                bf[nt][1] = __float_as_uint(Ws[col0 * ASTRIDE + kk + tig + 4]);
            }
#pragma unroll
            for (int mt = 0; mt < 4; mt++)
#pragma unroll
                for (int nt = 0; nt < 4; nt++)
                    mma_tf32(acc[mt][nt], af[mt], bf[nt]);
        }
        __syncthreads();
    }

#pragma unroll
    for (int mt = 0; mt < 4; mt++) {
        const long row0 = rowBase + wm + mt * 16 + gID;
#pragma unroll
        for (int nt = 0; nt < 4; nt++) {
            const int col = colBase + wn + nt * 8 + tig * 2;
            float bx = 0.f, by = 0.f;
            if (bias) { bx = bias[col]; by = bias[col + 1]; }
            *(float2*)(C + row0 * ldc + col) =
                make_float2(acc[mt][nt][0] + bx, acc[mt][nt][1] + by);
            *(float2*)(C + (row0 + 8) * ldc + col) =
                make_float2(acc[mt][nt][2] + bx, acc[mt][nt][3] + by);
        }
    }
}

// ===========================================================================
// Compress (both directions in one x pass).
// Block = (b, h_row): 32 consecutive tokens. 256 threads, 48KB smem.
// vh[(n_h*8+h)*64 + h_row*2+r], n_h = b*32 + w_col
// vw[(n_w*8+h)*64 + w_col*2+r], n_w = b*32 + h_row
// ===========================================================================
__global__ __launch_bounds__(256) void compress_kernel(
    const float* __restrict__ x,
    const float* __restrict__ WcH, const float* __restrict__ bcH,
    const float* __restrict__ WcW, const float* __restrict__ bcW,
    float* __restrict__ vh, float* __restrict__ vw)
{
    extern __shared__ float xs[];   // [32][384]
    const int blk = blockIdx.x;     // 0..2047
    const int b = blk >> 5;
    const int hrow = blk & 31;
    const long t0 = (long)blk * 32; // first token
    const int tid = threadIdx.x;

    for (int i = tid; i < 3072; i += 256)
        *(float4*)&xs[i * 4] = *(const float4*)&x[t0 * 384 + i * 4];
    __syncthreads();

    for (int idx = tid; idx < 1024; idx += 256) {
        const int dirW = idx >> 9;          // 0: H weights, 1: W weights
        const int rem = idx & 511;
        const int l = rem >> 4;             // w_col
        const int o = rem & 15;
        const float4* xr = (const float4*)&xs[l * 384];
        const float* Wc = dirW ? WcW : WcH;
        const float4* wr = (const float4*)&Wc[o * 384];
        float s = (dirW ? bcW : bcH)[o];
#pragma unroll 8
        for (int c4 = 0; c4 < 96; c4++) {
            float4 xv = xr[c4];
            float4 wv = wr[c4];
            s += xv.x * wv.x + xv.y * wv.y + xv.z * wv.z + xv.w * wv.w;
        }
        const int h = o >> 1, r = o & 1;
        if (dirW) {
            const int n = b * 32 + hrow;
            vw[(n * 8 + h) * 64 + l * 2 + r] = s;
        } else {
            const int n = b * 32 + l;
            vh[(n * 8 + h) * 64 + hrow * 2 + r] = s;
        }
    }
}

// ===========================================================================
// Softmax + apply per sequence. Grid 2048 blocks, 256 threads.
// Dynamic smem: smw[8][32][36] (9216) + xs[32][384] (12288) = 86016 B
// ===========================================================================
#define MA_SMEM_BYTES ((9216 + 12288) * 4)
#define SMW(h, l, j) smw[(h) * 1152 + (l) * 36 + (j)]

__global__ __launch_bounds__(256) void mixapply_kernel(
    const float* __restrict__ x,
    const float* __restrict__ logits,   // [(n*8+h)][1024], m = l*32+j
    float* __restrict__ out,
    int dir)
{
    extern __shared__ float sm[];
    float* smw = sm;            // [8][32][36]
    float* xs  = sm + 9216;     // [32][384]

    const int n = blockIdx.x;
    const int b = n >> 5;
    const int q = n & 31;
    long base;
    int stride;
    if (dir == 0) { base = ((long)b * 1024 + q) * 384; stride = 32 * 384; }
    else          { base = ((long)(b * 32 + q)) * 32 * 384; stride = 384; }

    const int tid = threadIdx.x;

    // stage x rows
    for (int i = tid; i < 3072; i += 256) {
        const int r = i / 96;
        const int c4 = i - r * 96;
        *(float4*)&xs[r * 384 + c4 * 4] =
            *(const float4*)&x[base + (long)r * stride + c4 * 4];
    }
    // stage logits -> smw (float4, j-groups of 4 within fixed l)
    const float4* lg = (const float4*)&logits[(long)n * 8192];
    for (int i = tid; i < 2048; i += 256) {
        const int h = i >> 8;
        const int m4 = i & 255;         // m = m4*4
        const int l = m4 >> 3;
        const int j = (m4 & 7) * 4;
        *(float4*)&SMW(h, l, j) = lg[i];
    }
    __syncthreads();

    // softmax over l for each (h, j)
    {
        const int h = tid >> 5;
        const int j = tid & 31;
        float mx = -1e30f;
#pragma unroll
        for (int l = 0; l < 32; l++) mx = fmaxf(mx, SMW(h, l, j));
        float sum = 0.f;
#pragma unroll
        for (int l = 0; l < 32; l++) {
            float e = __expf(SMW(h, l, j) - mx);
            SMW(h, l, j) = e;
            sum += e;
        }
        float inv = 1.f / sum;
#pragma unroll
        for (int l = 0; l < 32; l++) SMW(h, l, j) *= inv;
    }
    __syncthreads();

    // apply: y[j][c] = sum_l xs[l][c] * smw[c/48][l][j]
    for (int idx = tid; idx < 3072; idx += 256) {
        const int j  = idx / 96;
        const int c4 = idx - j * 96;
        const int h  = c4 / 12;
        float4 a = make_float4(0.f, 0.f, 0.f, 0.f);
#pragma unroll
        for (int l = 0; l < 32; l++) {
            const float w = SMW(h, l, j);
            const float4 xv = *(const float4*)&xs[l * 384 + c4 * 4];
            a.x += xv.x * w; a.y += xv.y * w;
            a.z += xv.z * w; a.w += xv.w * w;
        }
        *(float4*)&out[base + (long)j * stride + c4 * 4] = a;
    }
}
#undef SMW

// ===========================================================================
// Pool stage 1
// ===========================================================================
__global__ __launch_bounds__(384) void pool1_kernel(
    const float* __restrict__ h,
    const float* __restrict__ w,
    const float* __restrict__ c,
    float* __restrict__ part)
{
    const int b = blockIdx.x;
    const int ch = blockIdx.y;
    const int t = threadIdx.x;
    long base = ((long)b * 1024 + ch * 64) * 384 + t;
    float s = 0.f;
#pragma unroll 8
    for (int p = 0; p < 64; p++) {
        long o = base + (long)p * 384;
        s += h[o] + w[o] + c[o];
    }
    part[(b * 16 + ch) * 384 + t] = s;
}

// ===========================================================================
// Reweighting MLP + 3-way softmax
// ===========================================================================
__global__ __launch_bounds__(384) void mlp_kernel(
    const float* __restrict__ part,
    const float* __restrict__ Wr1, const float* __restrict__ br1,
    const float* __restrict__ Wr2, const float* __restrict__ br2,
    float* __restrict__ ga)
{
    __shared__ float pool_s[384];
    __shared__ float a1_s[96];
    const int b = blockIdx.x;
    const int t = threadIdx.x;

    float s = 0.f;
#pragma unroll
    for (int ch = 0; ch < 16; ch++) s += part[(b * 16 + ch) * 384 + t];
    pool_s[t] = s * (1.f / 1024.f);
    __syncthreads();

    if (t < 96) {
        float acc = br1[t];
        const float* wr = &Wr1[t * 384];
#pragma unroll 8
        for (int c = 0; c < 384; c++) acc += pool_s[c] * wr[c];
        a1_s[t] = 0.5f * acc * (1.f + erff(acc * 0.70710678118654752f));
    }
    __syncthreads();

    float v[3];
#pragma unroll
    for (int k = 0; k < 3; k++) {
        const int o = t * 3 + k;
        float acc = br2[o];
        const float* wr = &Wr2[o * 96];
#pragma unroll 8
        for (int i = 0; i < 96; i++) acc += a1_s[i] * wr[i];
        v[k] = acc;
    }
    float mx = fmaxf(v[0], fmaxf(v[1], v[2]));
    float e0 = __expf(v[0] - mx);
    float e1 = __expf(v[1] - mx);
    float e2 = __expf(v[2] - mx);
    float inv = 1.f / (e0 + e1 + e2);
    ga[(0 * 64 + b) * 384 + t] = e0 * inv;
    ga[(1 * 64 + b) * 384 + t] = e1 * inv;
    ga[(2 * 64 + b) * 384 + t] = e2 * inv;
}

// ===========================================================================
// Blend (in place into c)
// ===========================================================================
__global__ __launch_bounds__(256) void blend_kernel(
    const float* __restrict__ h,
    const float* __restrict__ w,
    float* __restrict__ c,
    const float* __restrict__ ga)
{
    const long i4 = (long)blockIdx.x * blockDim.x + threadIdx.x;
    if (i4 >= (NTOK / 4)) return;
    const long e = i4 * 4;
    const int b = (int)(e / (1024 * 384));
    const int ci = (int)(e % 384);

    float4 h4 = *(const float4*)&h[e];
    float4 w4 = *(const float4*)&w[e];
    float4 c4 = *(const float4*)&c[e];
    float4 a0 = *(const float4*)&ga[(0 * 64 + b) * 384 + ci];
    float4 a1 = *(const float4*)&ga[(1 * 64 + b) * 384 + ci];
    float4 a2 = *(const float4*)&ga[(2 * 64 + b) * 384 + ci];
    float4 r;
    r.x = h4.x * a0.x + w4.x * a1.x + c4.x * a2.x;
    r.y = h4.y * a0.y + w4.y * a1.y + c4.y * a2.y;
    r.z = h4.z * a0.z + w4.z * a1.z + c4.z * a2.z;
    r.w = h4.w * a0.w + w4.w * a1.w + c4.w * a2.w;
    *(float4*)&c[e] = r;
}

// ===========================================================================
// Launch
// ===========================================================================
extern "C" void kernel_launch(void* const* d_in, const int* in_sizes, int n_in,
                              void* d_out, int out_size)
{
    const float* x     = (const float*)d_in[0];
    const float* Wc_h  = (const float*)d_in[1];
    const float* bc_h  = (const float*)d_in[2];
    const float* Wg_h  = (const float*)d_in[3];
    const float* bg_h  = (const float*)d_in[4];
    const float* Wo_h  = (const float*)d_in[5];
    const float* bo_h  = (const float*)d_in[6];
    const float* Wc_w  = (const float*)d_in[7];
    const float* bc_w  = (const float*)d_in[8];
    const float* Wg_w  = (const float*)d_in[9];
    const float* bg_w  = (const float*)d_in[10];
    const float* Wo_w  = (const float*)d_in[11];
    const float* bo_w  = (const float*)d_in[12];
    const float* Wmlpc = (const float*)d_in[13];
    const float* Wr1   = (const float*)d_in[14];
    const float* br1   = (const float*)d_in[15];
    const float* Wr2   = (const float*)d_in[16];
    const float* br2   = (const float*)d_in[17];
    const float* Wp    = (const float*)d_in[18];
    const float* bp    = (const float*)d_in[19];
    float* out = (float*)d_out;

    float *p_mid, *p_h, *p_w, *p_c, *p_part, *p_a, *p_vh, *p_vw, *p_lg;
    cudaGetSymbolAddress((void**)&p_mid,  g_mid);
    cudaGetSymbolAddress((void**)&p_h,    g_h);
    cudaGetSymbolAddress((void**)&p_w,    g_w);
    cudaGetSymbolAddress((void**)&p_c,    g_c);
    cudaGetSymbolAddress((void**)&p_part, g_part);
    cudaGetSymbolAddress((void**)&p_a,    g_a);
    cudaGetSymbolAddress((void**)&p_vh,   g_vh);
    cudaGetSymbolAddress((void**)&p_vw,   g_vw);
    cudaGetSymbolAddress((void**)&p_lg,   g_logits);

    cudaFuncSetAttribute(compress_kernel,
                         cudaFuncAttributeMaxDynamicSharedMemorySize, 49152);
    cudaFuncSetAttribute(mixapply_kernel,
                         cudaFuncAttributeMaxDynamicSharedMemorySize, MA_SMEM_BYTES);

    dim3 ggemm(3, NROWS / 128);    // 384-col GEMMs
    dim3 ggen(8, 128);             // generate GEMM: N=1024, M=16384

    // compress for both directions
    compress_kernel<<<2048, 256, 49152>>>(x, Wc_h, bc_h, Wc_w, bc_w, p_vh, p_vw);

    // H-direction: generate -> softmax+apply -> Wo_h
    gemm_mma_g<<<ggen, 256>>>(p_vh, 64, Wg_h, 64, bg_h, p_lg, 1024, 64);
    mixapply_kernel<<<2048, 256, MA_SMEM_BYTES>>>(x, p_lg, p_mid, 0);
    gemm_mma_g<<<ggemm, 256>>>(p_mid, 384, Wo_h, 384, bo_h, p_h, 384, 384);

    // W-direction
    gemm_mma_g<<<ggen, 256>>>(p_vw, 64, Wg_w, 64, bg_w, p_lg, 1024, 64);
    mixapply_kernel<<<2048, 256, MA_SMEM_BYTES>>>(x, p_lg, p_mid, 1);
    gemm_mma_g<<<ggemm, 256>>>(p_mid, 384, Wo_w, 384, bo_w, p_w, 384, 384);

    // channel path
    gemm_mma_g<<<ggemm, 256>>>(x, 384, Wmlpc, 384, nullptr, p_c, 384, 384);

    // pool + MLP + blend
    pool1_kernel<<<dim3(64, 16), 384>>>(p_h, p_w, p_c, p_part);
    mlp_kernel<<<64, 384>>>(p_part, Wr1, br1, Wr2, br2, p_a);
    blend_kernel<<<(NTOK / 4 + 255) / 256, 256>>>(p_h, p_w, p_c, p_a);

    // final projection
    gemm_mma_g<<<ggemm, 256>>>(p_c, 384, Wp, 384, bp, out, 384, 384);
}

// round 5
// speedup vs baseline: 2.6801x; 1.0804x over previous
#include <cuda_runtime.h>
#include <cuda_bf16.h>
#include <math.h>
#include <stdint.h>

// ---------------------------------------------------------------------------
// Problem constants: B=64, RES=32, DIM=384, NH=8, RD=2
// ---------------------------------------------------------------------------
#define NTOK   25165824   // 64*32*32*384
#define NROWS  65536
#define CDIM   384

// Scratch (device globals; allocation-free)
__device__ float g_mid[NTOK];
__device__ float g_h[NTOK];
__device__ float g_w[NTOK];
__device__ float g_c[NTOK];
__device__ float g_part[64 * 16 * 384];
__device__ float g_a[3 * 64 * 384];
__device__ float g_vh[2048 * 8 * 64];
__device__ float g_vw[2048 * 8 * 64];
__device__ float g_logits[16384 * 1024];

__device__ __forceinline__ float tf32_rna(float x) {
    uint32_t u;
    asm("cvt.rna.tf32.f32 %0, %1;" : "=r"(u) : "f"(x));
    return __uint_as_float(u);
}
__device__ __forceinline__ uint32_t tf32_rna_u(float x) {
    uint32_t u;
    asm("cvt.rna.tf32.f32 %0, %1;" : "=r"(u) : "f"(x));
    return u;
}

__device__ __forceinline__ uint32_t smem_u32(const void* p) {
    uint32_t a;
    asm("{ .reg .u64 t; cvta.to.shared.u64 t, %1; cvt.u32.u64 %0, t; }"
        : "=r"(a) : "l"(p));
    return a;
}

__device__ __forceinline__ void cp_async16(uint32_t dst, const void* src) {
    asm volatile("cp.async.ca.shared.global [%0], [%1], 16;"
                 :: "r"(dst), "l"(src));
}
__device__ __forceinline__ void cp_commit() {
    asm volatile("cp.async.commit_group;");
}
template <int N>
__device__ __forceinline__ void cp_wait() {
    asm volatile("cp.async.wait_group %0;" :: "n"(N));
}

__device__ __forceinline__ void mma_tf32(float* d, const uint32_t* a, const uint32_t* b) {
    asm volatile(
        "mma.sync.aligned.m16n8k8.row.col.f32.tf32.tf32.f32 "
        "{%0,%1,%2,%3}, {%4,%5,%6,%7}, {%8,%9}, {%0,%1,%2,%3};"
        : "+f"(d[0]), "+f"(d[1]), "+f"(d[2]), "+f"(d[3])
        : "r"(a[0]), "r"(a[1]), "r"(a[2]), "r"(a[3]), "r"(b[0]), "r"(b[1]));
}

// ===========================================================================
// Generic tensor-core tf32 GEMM (NT), cp.async double-buffered.
// C[M,N] = A[M,K] * W[N,K]^T (+bias)
// Block tile 128x128, BK=32, 256 threads / 8 warps (2x4), warp tile 64x32.
// Grid (N/128, M/128). Requires M%128==0, N%128==0, K%32==0,
// lda/ldw row bytes multiple of 16.
// Dynamic smem: 2 stages x (As 128x36 + Ws 128x36) floats = 73728 B.
// ===========================================================================
#define ASTRIDE 36
#define STAGE_F (128 * ASTRIDE)
#define GEMM_SMEM_BYTES (4 * STAGE_F * 4)

__global__ __launch_bounds__(256, 2) void gemm_mma_g(
    const float* __restrict__ A, int lda,
    const float* __restrict__ W, int ldw,
    const float* __restrict__ bias,   // may be null
    float* __restrict__ C, int ldc, int K)
{
    extern __shared__ float smg[];
    // layout: stage0 As | stage0 Ws | stage1 As | stage1 Ws

    const int tid  = threadIdx.x;
    const int lane = tid & 31;
    const int wid  = tid >> 5;
    const int gID  = lane >> 2;
    const int tig  = lane & 3;
    const int wm   = (wid >> 2) * 64;
    const int wn   = (wid & 3) * 32;

    const long rowBase = (long)blockIdx.y * 128;
    const int  colBase = blockIdx.x * 128;
    const float* Abase = A + rowBase * lda;
    const float* Wbase = W + (long)colBase * ldw;

    // per-thread copy slots: 4 chunks for A, 4 for W
    const int cr = tid >> 1;                  // 0..127 row pairs? no:
    // idx scheme as before: idx = tid + s*256 ; r = idx>>3 ; g = (idx&7)*4
    const uint32_t smem_base = smem_u32(smg);

    float acc[4][4][4];
#pragma unroll
    for (int i = 0; i < 4; i++)
#pragma unroll
        for (int j = 0; j < 4; j++)
#pragma unroll
            for (int r = 0; r < 4; r++) acc[i][j][r] = 0.f;

    const int nk = K >> 5;

    // --- issue tile 0 ---
    {
        const int kt = 0;
#pragma unroll
        for (int s = 0; s < 4; s++) {
            const int idx = tid + s * 256;
            const int r = idx >> 3;
            const int g = (idx & 7) * 4;
            const uint32_t soff = (uint32_t)(r * ASTRIDE + g) * 4u;
            cp_async16(smem_base + soff, Abase + (long)r * lda + kt + g);
            cp_async16(smem_base + (uint32_t)STAGE_F * 4u + soff,
                       Wbase + (long)r * ldw + kt + g);
        }
        cp_commit();
    }

#pragma unroll 1
    for (int kti = 0; kti < nk; kti++) {
        const int st = kti & 1;
        // prefetch next tile into other stage
        if (kti + 1 < nk) {
            const int kt = (kti + 1) << 5;
            const uint32_t stoff = (uint32_t)((st ^ 1) * 2 * STAGE_F) * 4u;
#pragma unroll
            for (int s = 0; s < 4; s++) {
                const int idx = tid + s * 256;
                const int r = idx >> 3;
                const int g = (idx & 7) * 4;
                const uint32_t soff = (uint32_t)(r * ASTRIDE + g) * 4u;
                cp_async16(smem_base + stoff + soff,
                           Abase + (long)r * lda + kt + g);
                cp_async16(smem_base + stoff + (uint32_t)STAGE_F * 4u + soff,
                           Wbase + (long)r * ldw + kt + g);
            }
            cp_commit();
            cp_wait<1>();   // current tile (older group) complete
        } else {
            cp_wait<0>();
        }
        __syncthreads();

        const float* As = smg + st * 2 * STAGE_F;
        const float* Ws = As + STAGE_F;

#pragma unroll
        for (int kk = 0; kk < 32; kk += 8) {
            uint32_t af[4][4], bf[4][2];
#pragma unroll
            for (int mt = 0; mt < 4; mt++) {
                const int row0 = wm + mt * 16 + gID;
                af[mt][0] = tf32_rna_u(As[row0 * ASTRIDE + kk + tig]);
                af[mt][1] = tf32_rna_u(As[(row0 + 8) * ASTRIDE + kk + tig]);
                af[mt][2] = tf32_rna_u(As[row0 * ASTRIDE + kk + tig + 4]);
                af[mt][3] = tf32_rna_u(As[(row0 + 8) * ASTRIDE + kk + tig + 4]);
            }
#pragma unroll
            for (int nt = 0; nt < 4; nt++) {
                const int col0 = wn + nt * 8 + gID;
                bf[nt][0] = tf32_rna_u(Ws[col0 * ASTRIDE + kk + tig]);
                bf[nt][1] = tf32_rna_u(Ws[col0 * ASTRIDE + kk + tig + 4]);
            }
#pragma unroll
            for (int mt = 0; mt < 4; mt++)
#pragma unroll
                for (int nt = 0; nt < 4; nt++)
                    mma_tf32(acc[mt][nt], af[mt], bf[nt]);
        }
        __syncthreads();
    }

#pragma unroll
    for (int mt = 0; mt < 4; mt++) {
        const long row0 = rowBase + wm + mt * 16 + gID;
#pragma unroll
        for (int nt = 0; nt < 4; nt++) {
            const int col = colBase + wn + nt * 8 + tig * 2;
            float bx = 0.f, by = 0.f;
            if (bias) { bx = bias[col]; by = bias[col + 1]; }
            *(float2*)(C + row0 * ldc + col) =
                make_float2(acc[mt][nt][0] + bx, acc[mt][nt][1] + by);
            *(float2*)(C + (row0 + 8) * ldc + col) =
                make_float2(acc[mt][nt][2] + bx, acc[mt][nt][3] + by);
        }
    }
}

// ===========================================================================
// Compress (both directions in one x pass).
// ===========================================================================
__global__ __launch_bounds__(256) void compress_kernel(
    const float* __restrict__ x,
    const float* __restrict__ WcH, const float* __restrict__ bcH,
    const float* __restrict__ WcW, const float* __restrict__ bcW,
    float* __restrict__ vh, float* __restrict__ vw)
{
    extern __shared__ float xs[];   // [32][384]
    const int blk = blockIdx.x;
    const int b = blk >> 5;
    const int hrow = blk & 31;
    const long t0 = (long)blk * 32;
    const int tid = threadIdx.x;

    for (int i = tid; i < 3072; i += 256)
        *(float4*)&xs[i * 4] = *(const float4*)&x[t0 * 384 + i * 4];
    __syncthreads();

    for (int idx = tid; idx < 1024; idx += 256) {
        const int dirW = idx >> 9;
        const int rem = idx & 511;
        const int l = rem >> 4;
        const int o = rem & 15;
        const float4* xr = (const float4*)&xs[l * 384];
        const float* Wc = dirW ? WcW : WcH;
        const float4* wr = (const float4*)&Wc[o * 384];
        float s = (dirW ? bcW : bcH)[o];
#pragma unroll 8
        for (int c4 = 0; c4 < 96; c4++) {
            float4 xv = xr[c4];
            float4 wv = wr[c4];
            s += xv.x * wv.x + xv.y * wv.y + xv.z * wv.z + xv.w * wv.w;
        }
        const int h = o >> 1, r = o & 1;
        if (dirW) {
            const int n = b * 32 + hrow;
            vw[(n * 8 + h) * 64 + l * 2 + r] = s;
        } else {
            const int n = b * 32 + l;
            vh[(n * 8 + h) * 64 + hrow * 2 + r] = s;
        }
    }
}

// ===========================================================================
// Softmax + apply per sequence.
// ===========================================================================
#define MA_SMEM_BYTES ((9216 + 12288) * 4)
#define SMW(h, l, j) smw[(h) * 1152 + (l) * 36 + (j)]

__global__ __launch_bounds__(256) void mixapply_kernel(
    const float* __restrict__ x,
    const float* __restrict__ logits,
    float* __restrict__ out,
    int dir)
{
    extern __shared__ float sm[];
    float* smw = sm;            // [8][32][36]
    float* xs  = sm + 9216;     // [32][384]

    const int n = blockIdx.x;
    const int b = n >> 5;
    const int q = n & 31;
    long base;
    int stride;
    if (dir == 0) { base = ((long)b * 1024 + q) * 384; stride = 32 * 384; }
    else          { base = ((long)(b * 32 + q)) * 32 * 384; stride = 384; }

    const int tid = threadIdx.x;

    for (int i = tid; i < 3072; i += 256) {
        const int r = i / 96;
        const int c4 = i - r * 96;
        *(float4*)&xs[r * 384 + c4 * 4] =
            *(const float4*)&x[base + (long)r * stride + c4 * 4];
    }
    const float4* lg = (const float4*)&logits[(long)n * 8192];
    for (int i = tid; i < 2048; i += 256) {
        const int h = i >> 8;
        const int m4 = i & 255;
        const int l = m4 >> 3;
        const int j = (m4 & 7) * 4;
        *(float4*)&SMW(h, l, j) = lg[i];
    }
    __syncthreads();

    {
        const int h = tid >> 5;
        const int j = tid & 31;
        float mx = -1e30f;
#pragma unroll
        for (int l = 0; l < 32; l++) mx = fmaxf(mx, SMW(h, l, j));
        float sum = 0.f;
#pragma unroll
        for (int l = 0; l < 32; l++) {
            float e = __expf(SMW(h, l, j) - mx);
            SMW(h, l, j) = e;
            sum += e;
        }
        float inv = 1.f / sum;
#pragma unroll
        for (int l = 0; l < 32; l++) SMW(h, l, j) *= inv;
    }
    __syncthreads();

    for (int idx = tid; idx < 3072; idx += 256) {
        const int j  = idx / 96;
        const int c4 = idx - j * 96;
        const int h  = c4 / 12;
        float4 a = make_float4(0.f, 0.f, 0.f, 0.f);
#pragma unroll
        for (int l = 0; l < 32; l++) {
            const float w = SMW(h, l, j);
            const float4 xv = *(const float4*)&xs[l * 384 + c4 * 4];
            a.x += xv.x * w; a.y += xv.y * w;
            a.z += xv.z * w; a.w += xv.w * w;
        }
        *(float4*)&out[base + (long)j * stride + c4 * 4] = a;
    }
}
#undef SMW

// ===========================================================================
// Pool stage 1
// ===========================================================================
__global__ __launch_bounds__(384) void pool1_kernel(
    const float* __restrict__ h,
    const float* __restrict__ w,
    const float* __restrict__ c,
    float* __restrict__ part)
{
    const int b = blockIdx.x;
    const int ch = blockIdx.y;
    const int t = threadIdx.x;
    long base = ((long)b * 1024 + ch * 64) * 384 + t;
    float s = 0.f;
#pragma unroll 8
    for (int p = 0; p < 64; p++) {
        long o = base + (long)p * 384;
        s += h[o] + w[o] + c[o];
    }
    part[(b * 16 + ch) * 384 + t] = s;
}

// ===========================================================================
// Reweighting MLP + 3-way softmax
// ===========================================================================
__global__ __launch_bounds__(384) void mlp_kernel(
    const float* __restrict__ part,
    const float* __restrict__ Wr1, const float* __restrict__ br1,
    const float* __restrict__ Wr2, const float* __restrict__ br2,
    float* __restrict__ ga)
{
    __shared__ float pool_s[384];
    __shared__ float a1_s[96];
    const int b = blockIdx.x;
    const int t = threadIdx.x;

    float s = 0.f;
#pragma unroll
    for (int ch = 0; ch < 16; ch++) s += part[(b * 16 + ch) * 384 + t];
    pool_s[t] = s * (1.f / 1024.f);
    __syncthreads();

    if (t < 96) {
        float acc = br1[t];
        const float* wr = &Wr1[t * 384];
#pragma unroll 8
        for (int c = 0; c < 384; c++) acc += pool_s[c] * wr[c];
        a1_s[t] = 0.5f * acc * (1.f + erff(acc * 0.70710678118654752f));
    }
    __syncthreads();

    float v[3];
#pragma unroll
    for (int k = 0; k < 3; k++) {
        const int o = t * 3 + k;
        float acc = br2[o];
        const float* wr = &Wr2[o * 96];
#pragma unroll 8
        for (int i = 0; i < 96; i++) acc += a1_s[i] * wr[i];
        v[k] = acc;
    }
    float mx = fmaxf(v[0], fmaxf(v[1], v[2]));
    float e0 = __expf(v[0] - mx);
    float e1 = __expf(v[1] - mx);
    float e2 = __expf(v[2] - mx);
    float inv = 1.f / (e0 + e1 + e2);
    ga[(0 * 64 + b) * 384 + t] = e0 * inv;
    ga[(1 * 64 + b) * 384 + t] = e1 * inv;
    ga[(2 * 64 + b) * 384 + t] = e2 * inv;
}

// ===========================================================================
// Blend (in place into c)
// ===========================================================================
__global__ __launch_bounds__(256) void blend_kernel(
    const float* __restrict__ h,
    const float* __restrict__ w,
    float* __restrict__ c,
    const float* __restrict__ ga)
{
    const long i4 = (long)blockIdx.x * blockDim.x + threadIdx.x;
    if (i4 >= (NTOK / 4)) return;
    const long e = i4 * 4;
    const int b = (int)(e / (1024 * 384));
    const int ci = (int)(e % 384);

    float4 h4 = *(const float4*)&h[e];
    float4 w4 = *(const float4*)&w[e];
    float4 c4 = *(const float4*)&c[e];
    float4 a0 = *(const float4*)&ga[(0 * 64 + b) * 384 + ci];
    float4 a1 = *(const float4*)&ga[(1 * 64 + b) * 384 + ci];
    float4 a2 = *(const float4*)&ga[(2 * 64 + b) * 384 + ci];
    float4 r;
    r.x = h4.x * a0.x + w4.x * a1.x + c4.x * a2.x;
    r.y = h4.y * a0.y + w4.y * a1.y + c4.y * a2.y;
    r.z = h4.z * a0.z + w4.z * a1.z + c4.z * a2.z;
    r.w = h4.w * a0.w + w4.w * a1.w + c4.w * a2.w;
    *(float4*)&c[e] = r;
}

// ===========================================================================
// Launch
// ===========================================================================
extern "C" void kernel_launch(void* const* d_in, const int* in_sizes, int n_in,
                              void* d_out, int out_size)
{
    const float* x     = (const float*)d_in[0];
    const float* Wc_h  = (const float*)d_in[1];
    const float* bc_h  = (const float*)d_in[2];
    const float* Wg_h  = (const float*)d_in[3];
    const float* bg_h  = (const float*)d_in[4];
    const float* Wo_h  = (const float*)d_in[5];
    const float* bo_h  = (const float*)d_in[6];
    const float* Wc_w  = (const float*)d_in[7];
    const float* bc_w  = (const float*)d_in[8];
    const float* Wg_w  = (const float*)d_in[9];
    const float* bg_w  = (const float*)d_in[10];
    const float* Wo_w  = (const float*)d_in[11];
    const float* bo_w  = (const float*)d_in[12];
    const float* Wmlpc = (const float*)d_in[13];
    const float* Wr1   = (const float*)d_in[14];
    const float* br1   = (const float*)d_in[15];
    const float* Wr2   = (const float*)d_in[16];
    const float* br2   = (const float*)d_in[17];
    const float* Wp    = (const float*)d_in[18];
    const float* bp    = (const float*)d_in[19];
    float* out = (float*)d_out;

    float *p_mid, *p_h, *p_w, *p_c, *p_part, *p_a, *p_vh, *p_vw, *p_lg;
    cudaGetSymbolAddress((void**)&p_mid,  g_mid);
    cudaGetSymbolAddress((void**)&p_h,    g_h);
    cudaGetSymbolAddress((void**)&p_w,    g_w);
    cudaGetSymbolAddress((void**)&p_c,    g_c);
    cudaGetSymbolAddress((void**)&p_part, g_part);
    cudaGetSymbolAddress((void**)&p_a,    g_a);
    cudaGetSymbolAddress((void**)&p_vh,   g_vh);
    cudaGetSymbolAddress((void**)&p_vw,   g_vw);
    cudaGetSymbolAddress((void**)&p_lg,   g_logits);

    cudaFuncSetAttribute(gemm_mma_g,
                         cudaFuncAttributeMaxDynamicSharedMemorySize,
                         GEMM_SMEM_BYTES);
    cudaFuncSetAttribute(compress_kernel,
                         cudaFuncAttributeMaxDynamicSharedMemorySize, 49152);
    cudaFuncSetAttribute(mixapply_kernel,
                         cudaFuncAttributeMaxDynamicSharedMemorySize, MA_SMEM_BYTES);

    dim3 ggemm(3, NROWS / 128);
    dim3 ggen(8, 128);

    compress_kernel<<<2048, 256, 49152>>>(x, Wc_h, bc_h, Wc_w, bc_w, p_vh, p_vw);

    // H-direction
    gemm_mma_g<<<ggen, 256, GEMM_SMEM_BYTES>>>(p_vh, 64, Wg_h, 64, bg_h, p_lg, 1024, 64);
    mixapply_kernel<<<2048, 256, MA_SMEM_BYTES>>>(x, p_lg, p_mid, 0);
    gemm_mma_g<<<ggemm, 256, GEMM_SMEM_BYTES>>>(p_mid, 384, Wo_h, 384, bo_h, p_h, 384, 384);

    // W-direction
    gemm_mma_g<<<ggen, 256, GEMM_SMEM_BYTES>>>(p_vw, 64, Wg_w, 64, bg_w, p_lg, 1024, 64);
    mixapply_kernel<<<2048, 256, MA_SMEM_BYTES>>>(x, p_lg, p_mid, 1);
    gemm_mma_g<<<ggemm, 256, GEMM_SMEM_BYTES>>>(p_mid, 384, Wo_w, 384, bo_w, p_w, 384, 384);

    // channel path
    gemm_mma_g<<<ggemm, 256, GEMM_SMEM_BYTES>>>(x, 384, Wmlpc, 384, nullptr, p_c, 384, 384);

    // pool + MLP + blend
    pool1_kernel<<<dim3(64, 16), 384>>>(p_h, p_w, p_c, p_part);
    mlp_kernel<<<64, 384>>>(p_part, Wr1, br1, Wr2, br2, p_a);
    blend_kernel<<<(NTOK / 4 + 255) / 256, 256>>>(p_h, p_w, p_c, p_a);

    // final projection
    gemm_mma_g<<<ggemm, 256, GEMM_SMEM_BYTES>>>(p_c, 384, Wp, 384, bp, out, 384, 384);
}

// round 6
// speedup vs baseline: 2.7176x; 1.0140x over previous
#include <cuda_runtime.h>
#include <cuda_bf16.h>
#include <math.h>
#include <stdint.h>

// ---------------------------------------------------------------------------
// Problem constants: B=64, RES=32, DIM=384, NH=8, RD=2
// ---------------------------------------------------------------------------
#define NTOK   25165824   // 64*32*32*384
#define NROWS  65536
#define CDIM   384

// Scratch (device globals; allocation-free)
__device__ float g_mid[NTOK];
__device__ float g_h[NTOK];
__device__ float g_w[NTOK];
__device__ float g_c[NTOK];
__device__ float g_part[64 * 16 * 384];
__device__ float g_a[3 * 64 * 384];
__device__ float g_vh[2048 * 8 * 64];
__device__ float g_vw[2048 * 8 * 64];
__device__ float g_logits[16384 * 1024];
__device__ float g_wr[3 * 147456];   // rounded Wo_h | Wo_w | Wp
__device__ float g_wgr[2 * 65536];   // rounded Wg_h | Wg_w

__device__ __forceinline__ float tf32_rna(float x) {
    uint32_t u;
    asm("cvt.rna.tf32.f32 %0, %1;" : "=r"(u) : "f"(x));
    return __uint_as_float(u);
}
__device__ __forceinline__ uint32_t tf32_rna_u(float x) {
    uint32_t u;
    asm("cvt.rna.tf32.f32 %0, %1;" : "=r"(u) : "f"(x));
    return u;
}

__device__ __forceinline__ uint32_t smem_u32(const void* p) {
    uint32_t a;
    asm("{ .reg .u64 t; cvta.to.shared.u64 t, %1; cvt.u32.u64 %0, t; }"
        : "=r"(a) : "l"(p));
    return a;
}

__device__ __forceinline__ void cp_async16(uint32_t dst, const void* src) {
    asm volatile("cp.async.ca.shared.global [%0], [%1], 16;"
                 :: "r"(dst), "l"(src));
}
__device__ __forceinline__ void cp_commit() {
    asm volatile("cp.async.commit_group;");
}
template <int N>
__device__ __forceinline__ void cp_wait() {
    asm volatile("cp.async.wait_group %0;" :: "n"(N));
}

__device__ __forceinline__ void mma_tf32(float* d, const uint32_t* a, const uint32_t* b) {
    asm volatile(
        "mma.sync.aligned.m16n8k8.row.col.f32.tf32.tf32.f32 "
        "{%0,%1,%2,%3}, {%4,%5,%6,%7}, {%8,%9}, {%0,%1,%2,%3};"
        : "+f"(d[0]), "+f"(d[1]), "+f"(d[2]), "+f"(d[3])
        : "r"(a[0]), "r"(a[1]), "r"(a[2]), "r"(a[3]), "r"(b[0]), "r"(b[1]));
}

// ===========================================================================
// tf32 rounding copy kernels (weights; one-time)
// ===========================================================================
__global__ __launch_bounds__(256) void round3_kernel(
    const float* __restrict__ a, const float* __restrict__ b,
    const float* __restrict__ c, float* __restrict__ dst)
{
    const int seg = blockIdx.y;
    const float* src = seg == 0 ? a : (seg == 1 ? b : c);
    const int i = blockIdx.x * 256 + threadIdx.x;     // float4 index, 36864 per seg
    if (i >= 36864) return;
    float4 v = *(const float4*)(src + i * 4);
    v.x = tf32_rna(v.x); v.y = tf32_rna(v.y);
    v.z = tf32_rna(v.z); v.w = tf32_rna(v.w);
    *(float4*)(dst + seg * 147456 + i * 4) = v;
}

__global__ __launch_bounds__(256) void round2_kernel(
    const float* __restrict__ a, const float* __restrict__ b,
    float* __restrict__ dst)
{
    const int seg = blockIdx.y;
    const float* src = seg == 0 ? a : b;
    const int i = blockIdx.x * 256 + threadIdx.x;     // float4 index, 16384 per seg
    if (i >= 16384) return;
    float4 v = *(const float4*)(src + i * 4);
    v.x = tf32_rna(v.x); v.y = tf32_rna(v.y);
    v.z = tf32_rna(v.z); v.w = tf32_rna(v.w);
    *(float4*)(dst + seg * 65536 + i * 4) = v;
}

// ===========================================================================
// Generic tensor-core tf32 GEMM (NT), cp.async double-buffered.
// C[M,N] = A[M,K] * W[N,K]^T (+bias)
// CVT=true: round operands inline; CVT=false: operands pre-rounded tf32.
// ===========================================================================
#define ASTRIDE 36
#define STAGE_F (128 * ASTRIDE)
#define GEMM_SMEM_BYTES (4 * STAGE_F * 4)

template <bool CVT>
__global__ __launch_bounds__(256, 2) void gemm_mma_t(
    const float* __restrict__ A, int lda,
    const float* __restrict__ W, int ldw,
    const float* __restrict__ bias,   // may be null
    float* __restrict__ C, int ldc, int K)
{
    extern __shared__ float smg[];

    const int tid  = threadIdx.x;
    const int lane = tid & 31;
    const int wid  = tid >> 5;
    const int gID  = lane >> 2;
    const int tig  = lane & 3;
    const int wm   = (wid >> 2) * 64;
    const int wn   = (wid & 3) * 32;

    const long rowBase = (long)blockIdx.y * 128;
    const int  colBase = blockIdx.x * 128;
    const float* Abase = A + rowBase * lda;
    const float* Wbase = W + (long)colBase * ldw;

    const uint32_t smem_base = smem_u32(smg);

    float acc[4][4][4];
#pragma unroll
    for (int i = 0; i < 4; i++)
#pragma unroll
        for (int j = 0; j < 4; j++)
#pragma unroll
            for (int r = 0; r < 4; r++) acc[i][j][r] = 0.f;

    const int nk = K >> 5;

    {
#pragma unroll
        for (int s = 0; s < 4; s++) {
            const int idx = tid + s * 256;
            const int r = idx >> 3;
            const int g = (idx & 7) * 4;
            const uint32_t soff = (uint32_t)(r * ASTRIDE + g) * 4u;
            cp_async16(smem_base + soff, Abase + (long)r * lda + g);
            cp_async16(smem_base + (uint32_t)STAGE_F * 4u + soff,
                       Wbase + (long)r * ldw + g);
        }
        cp_commit();
    }

#pragma unroll 1
    for (int kti = 0; kti < nk; kti++) {
        const int st = kti & 1;
        if (kti + 1 < nk) {
            const int kt = (kti + 1) << 5;
            const uint32_t stoff = (uint32_t)((st ^ 1) * 2 * STAGE_F) * 4u;
#pragma unroll
            for (int s = 0; s < 4; s++) {
                const int idx = tid + s * 256;
                const int r = idx >> 3;
                const int g = (idx & 7) * 4;
                const uint32_t soff = (uint32_t)(r * ASTRIDE + g) * 4u;
                cp_async16(smem_base + stoff + soff,
                           Abase + (long)r * lda + kt + g);
                cp_async16(smem_base + stoff + (uint32_t)STAGE_F * 4u + soff,
                           Wbase + (long)r * ldw + kt + g);
            }
            cp_commit();
            cp_wait<1>();
        } else {
            cp_wait<0>();
        }
        __syncthreads();

        const float* As = smg + st * 2 * STAGE_F;
        const float* Ws = As + STAGE_F;

#pragma unroll
        for (int kk = 0; kk < 32; kk += 8) {
            uint32_t af[4][4], bf[4][2];
#pragma unroll
            for (int mt = 0; mt < 4; mt++) {
                const int row0 = wm + mt * 16 + gID;
                if (CVT) {
                    af[mt][0] = tf32_rna_u(As[row0 * ASTRIDE + kk + tig]);
                    af[mt][1] = tf32_rna_u(As[(row0 + 8) * ASTRIDE + kk + tig]);
                    af[mt][2] = tf32_rna_u(As[row0 * ASTRIDE + kk + tig + 4]);
                    af[mt][3] = tf32_rna_u(As[(row0 + 8) * ASTRIDE + kk + tig + 4]);
                } else {
                    af[mt][0] = __float_as_uint(As[row0 * ASTRIDE + kk + tig]);
                    af[mt][1] = __float_as_uint(As[(row0 + 8) * ASTRIDE + kk + tig]);
                    af[mt][2] = __float_as_uint(As[row0 * ASTRIDE + kk + tig + 4]);
                    af[mt][3] = __float_as_uint(As[(row0 + 8) * ASTRIDE + kk + tig + 4]);
                }
            }
#pragma unroll
            for (int nt = 0; nt < 4; nt++) {
                const int col0 = wn + nt * 8 + gID;
                if (CVT) {
                    bf[nt][0] = tf32_rna_u(Ws[col0 * ASTRIDE + kk + tig]);
                    bf[nt][1] = tf32_rna_u(Ws[col0 * ASTRIDE + kk + tig + 4]);
                } else {
                    bf[nt][0] = __float_as_uint(Ws[col0 * ASTRIDE + kk + tig]);
                    bf[nt][1] = __float_as_uint(Ws[col0 * ASTRIDE + kk + tig + 4]);
                }
            }
#pragma unroll
            for (int mt = 0; mt < 4; mt++)
#pragma unroll
                for (int nt = 0; nt < 4; nt++)
                    mma_tf32(acc[mt][nt], af[mt], bf[nt]);
        }
        __syncthreads();
    }

#pragma unroll
    for (int mt = 0; mt < 4; mt++) {
        const long row0 = rowBase + wm + mt * 16 + gID;
#pragma unroll
        for (int nt = 0; nt < 4; nt++) {
            const int col = colBase + wn + nt * 8 + tig * 2;
            float bx = 0.f, by = 0.f;
            if (bias) { bx = bias[col]; by = bias[col + 1]; }
            *(float2*)(C + row0 * ldc + col) =
                make_float2(acc[mt][nt][0] + bx, acc[mt][nt][1] + by);
            *(float2*)(C + (row0 + 8) * ldc + col) =
                make_float2(acc[mt][nt][2] + bx, acc[mt][nt][3] + by);
        }
    }
}

// ===========================================================================
// Compress (both directions in one x pass). Outputs pre-rounded to tf32.
// ===========================================================================
__global__ __launch_bounds__(256) void compress_kernel(
    const float* __restrict__ x,
    const float* __restrict__ WcH, const float* __restrict__ bcH,
    const float* __restrict__ WcW, const float* __restrict__ bcW,
    float* __restrict__ vh, float* __restrict__ vw)
{
    extern __shared__ float xs[];   // [32][384]
    const int blk = blockIdx.x;
    const int b = blk >> 5;
    const int hrow = blk & 31;
    const long t0 = (long)blk * 32;
    const int tid = threadIdx.x;

    for (int i = tid; i < 3072; i += 256)
        *(float4*)&xs[i * 4] = *(const float4*)&x[t0 * 384 + i * 4];
    __syncthreads();

    for (int idx = tid; idx < 1024; idx += 256) {
        const int dirW = idx >> 9;
        const int rem = idx & 511;
        const int l = rem >> 4;
        const int o = rem & 15;
        const float4* xr = (const float4*)&xs[l * 384];
        const float* Wc = dirW ? WcW : WcH;
        const float4* wr = (const float4*)&Wc[o * 384];
        float s = (dirW ? bcW : bcH)[o];
#pragma unroll 8
        for (int c4 = 0; c4 < 96; c4++) {
            float4 xv = xr[c4];
            float4 wv = wr[c4];
            s += xv.x * wv.x + xv.y * wv.y + xv.z * wv.z + xv.w * wv.w;
        }
        s = tf32_rna(s);
        const int h = o >> 1, r = o & 1;
        if (dirW) {
            const int n = b * 32 + hrow;
            vw[(n * 8 + h) * 64 + l * 2 + r] = s;
        } else {
            const int n = b * 32 + l;
            vh[(n * 8 + h) * 64 + hrow * 2 + r] = s;
        }
    }
}

// ===========================================================================
// Softmax + apply per sequence. Output pre-rounded to tf32.
// ===========================================================================
#define MA_SMEM_BYTES ((9216 + 12288) * 4)
#define SMW(h, l, j) smw[(h) * 1152 + (l) * 36 + (j)]

__global__ __launch_bounds__(256) void mixapply_kernel(
    const float* __restrict__ x,
    const float* __restrict__ logits,
    float* __restrict__ out,
    int dir)
{
    extern __shared__ float sm[];
    float* smw = sm;            // [8][32][36]
    float* xs  = sm + 9216;     // [32][384]

    const int n = blockIdx.x;
    const int b = n >> 5;
    const int q = n & 31;
    long base;
    int stride;
    if (dir == 0) { base = ((long)b * 1024 + q) * 384; stride = 32 * 384; }
    else          { base = ((long)(b * 32 + q)) * 32 * 384; stride = 384; }

    const int tid = threadIdx.x;

    for (int i = tid; i < 3072; i += 256) {
        const int r = i / 96;
        const int c4 = i - r * 96;
        *(float4*)&xs[r * 384 + c4 * 4] =
            *(const float4*)&x[base + (long)r * stride + c4 * 4];
    }
    const float4* lg = (const float4*)&logits[(long)n * 8192];
    for (int i = tid; i < 2048; i += 256) {
        const int h = i >> 8;
        const int m4 = i & 255;
        const int l = m4 >> 3;
        const int j = (m4 & 7) * 4;
        *(float4*)&SMW(h, l, j) = lg[i];
    }
    __syncthreads();

    {
        const int h = tid >> 5;
        const int j = tid & 31;
        float mx = -1e30f;
#pragma unroll
        for (int l = 0; l < 32; l++) mx = fmaxf(mx, SMW(h, l, j));
        float sum = 0.f;
#pragma unroll
        for (int l = 0; l < 32; l++) {
            float e = __expf(SMW(h, l, j) - mx);
            SMW(h, l, j) = e;
            sum += e;
        }
        float inv = 1.f / sum;
#pragma unroll
        for (int l = 0; l < 32; l++) SMW(h, l, j) *= inv;
    }
    __syncthreads();

    for (int idx = tid; idx < 3072; idx += 256) {
        const int j  = idx / 96;
        const int c4 = idx - j * 96;
        const int h  = c4 / 12;
        float4 a = make_float4(0.f, 0.f, 0.f, 0.f);
#pragma unroll
        for (int l = 0; l < 32; l++) {
            const float w = SMW(h, l, j);
            const float4 xv = *(const float4*)&xs[l * 384 + c4 * 4];
            a.x += xv.x * w; a.y += xv.y * w;
            a.z += xv.z * w; a.w += xv.w * w;
        }
        a.x = tf32_rna(a.x); a.y = tf32_rna(a.y);
        a.z = tf32_rna(a.z); a.w = tf32_rna(a.w);
        *(float4*)&out[base + (long)j * stride + c4 * 4] = a;
    }
}
#undef SMW

// ===========================================================================
// Pool stage 1
// ===========================================================================
__global__ __launch_bounds__(384) void pool1_kernel(
    const float* __restrict__ h,
    const float* __restrict__ w,
    const float* __restrict__ c,
    float* __restrict__ part)
{
    const int b = blockIdx.x;
    const int ch = blockIdx.y;
    const int t = threadIdx.x;
    long base = ((long)b * 1024 + ch * 64) * 384 + t;
    float s = 0.f;
#pragma unroll 8
    for (int p = 0; p < 64; p++) {
        long o = base + (long)p * 384;
        s += h[o] + w[o] + c[o];
    }
    part[(b * 16 + ch) * 384 + t] = s;
}

// ===========================================================================
// Reweighting MLP + 3-way softmax
// ===========================================================================
__global__ __launch_bounds__(384) void mlp_kernel(
    const float* __restrict__ part,
    const float* __restrict__ Wr1, const float* __restrict__ br1,
    const float* __restrict__ Wr2, const float* __restrict__ br2,
    float* __restrict__ ga)
{
    __shared__ float pool_s[384];
    __shared__ float a1_s[96];
    const int b = blockIdx.x;
    const int t = threadIdx.x;

    float s = 0.f;
#pragma unroll
    for (int ch = 0; ch < 16; ch++) s += part[(b * 16 + ch) * 384 + t];
    pool_s[t] = s * (1.f / 1024.f);
    __syncthreads();

    if (t < 96) {
        float acc = br1[t];
        const float* wr = &Wr1[t * 384];
#pragma unroll 8
        for (int c = 0; c < 384; c++) acc += pool_s[c] * wr[c];
        a1_s[t] = 0.5f * acc * (1.f + erff(acc * 0.70710678118654752f));
    }
    __syncthreads();

    float v[3];
#pragma unroll
    for (int k = 0; k < 3; k++) {
        const int o = t * 3 + k;
        float acc = br2[o];
        const float* wr = &Wr2[o * 96];
#pragma unroll 8
        for (int i = 0; i < 96; i++) acc += a1_s[i] * wr[i];
        v[k] = acc;
    }
    float mx = fmaxf(v[0], fmaxf(v[1], v[2]));
    float e0 = __expf(v[0] - mx);
    float e1 = __expf(v[1] - mx);
    float e2 = __expf(v[2] - mx);
    float inv = 1.f / (e0 + e1 + e2);
    ga[(0 * 64 + b) * 384 + t] = e0 * inv;
    ga[(1 * 64 + b) * 384 + t] = e1 * inv;
    ga[(2 * 64 + b) * 384 + t] = e2 * inv;
}

// ===========================================================================
// Blend (in place into c); output pre-rounded to tf32 for final GEMM.
// ===========================================================================
__global__ __launch_bounds__(256) void blend_kernel(
    const float* __restrict__ h,
    const float* __restrict__ w,
    float* __restrict__ c,
    const float* __restrict__ ga)
{
    const long i4 = (long)blockIdx.x * blockDim.x + threadIdx.x;
    if (i4 >= (NTOK / 4)) return;
    const long e = i4 * 4;
    const int b = (int)(e / (1024 * 384));
    const int ci = (int)(e % 384);

    float4 h4 = *(const float4*)&h[e];
    float4 w4 = *(const float4*)&w[e];
    float4 c4 = *(const float4*)&c[e];
    float4 a0 = *(const float4*)&ga[(0 * 64 + b) * 384 + ci];
    float4 a1 = *(const float4*)&ga[(1 * 64 + b) * 384 + ci];
    float4 a2 = *(const float4*)&ga[(2 * 64 + b) * 384 + ci];
    float4 r;
    r.x = tf32_rna(h4.x * a0.x + w4.x * a1.x + c4.x * a2.x);
    r.y = tf32_rna(h4.y * a0.y + w4.y * a1.y + c4.y * a2.y);
    r.z = tf32_rna(h4.z * a0.z + w4.z * a1.z + c4.z * a2.z);
    r.w = tf32_rna(h4.w * a0.w + w4.w * a1.w + c4.w * a2.w);
    *(float4*)&c[e] = r;
}

// ===========================================================================
// Launch
// ===========================================================================
extern "C" void kernel_launch(void* const* d_in, const int* in_sizes, int n_in,
                              void* d_out, int out_size)
{
    const float* x     = (const float*)d_in[0];
    const float* Wc_h  = (const float*)d_in[1];
    const float* bc_h  = (const float*)d_in[2];
    const float* Wg_h  = (const float*)d_in[3];
    const float* bg_h  = (const float*)d_in[4];
    const float* Wo_h  = (const float*)d_in[5];
    const float* bo_h  = (const float*)d_in[6];
    const float* Wc_w  = (const float*)d_in[7];
    const float* bc_w  = (const float*)d_in[8];
    const float* Wg_w  = (const float*)d_in[9];
    const float* bg_w  = (const float*)d_in[10];
    const float* Wo_w  = (const float*)d_in[11];
    const float* bo_w  = (const float*)d_in[12];
    const float* Wmlpc = (const float*)d_in[13];
    const float* Wr1   = (const float*)d_in[14];
    const float* br1   = (const float*)d_in[15];
    const float* Wr2   = (const float*)d_in[16];
    const float* br2   = (const float*)d_in[17];
    const float* Wp    = (const float*)d_in[18];
    const float* bp    = (const float*)d_in[19];
    float* out = (float*)d_out;

    float *p_mid, *p_h, *p_w, *p_c, *p_part, *p_a, *p_vh, *p_vw, *p_lg, *p_wr, *p_wgr;
    cudaGetSymbolAddress((void**)&p_mid,  g_mid);
    cudaGetSymbolAddress((void**)&p_h,    g_h);
    cudaGetSymbolAddress((void**)&p_w,    g_w);
    cudaGetSymbolAddress((void**)&p_c,    g_c);
    cudaGetSymbolAddress((void**)&p_part, g_part);
    cudaGetSymbolAddress((void**)&p_a,    g_a);
    cudaGetSymbolAddress((void**)&p_vh,   g_vh);
    cudaGetSymbolAddress((void**)&p_vw,   g_vw);
    cudaGetSymbolAddress((void**)&p_lg,   g_logits);
    cudaGetSymbolAddress((void**)&p_wr,   g_wr);
    cudaGetSymbolAddress((void**)&p_wgr,  g_wgr);

    cudaFuncSetAttribute(gemm_mma_t<false>,
                         cudaFuncAttributeMaxDynamicSharedMemorySize, GEMM_SMEM_BYTES);
    cudaFuncSetAttribute(gemm_mma_t<true>,
                         cudaFuncAttributeMaxDynamicSharedMemorySize, GEMM_SMEM_BYTES);
    cudaFuncSetAttribute(compress_kernel,
                         cudaFuncAttributeMaxDynamicSharedMemorySize, 49152);
    cudaFuncSetAttribute(mixapply_kernel,
                         cudaFuncAttributeMaxDynamicSharedMemorySize, MA_SMEM_BYTES);

    dim3 ggemm(3, NROWS / 128);
    dim3 ggen(8, 128);

    // one-time weight rounding
    round3_kernel<<<dim3(144, 3), 256>>>(Wo_h, Wo_w, Wp, p_wr);
    round2_kernel<<<dim3(64, 2), 256>>>(Wg_h, Wg_w, p_wgr);

    compress_kernel<<<2048, 256, 49152>>>(x, Wc_h, bc_h, Wc_w, bc_w, p_vh, p_vw);

    // H-direction
    gemm_mma_t<false><<<ggen, 256, GEMM_SMEM_BYTES>>>(p_vh, 64, p_wgr, 64, bg_h, p_lg, 1024, 64);
    mixapply_kernel<<<2048, 256, MA_SMEM_BYTES>>>(x, p_lg, p_mid, 0);
    gemm_mma_t<false><<<ggemm, 256, GEMM_SMEM_BYTES>>>(p_mid, 384, p_wr, 384, bo_h, p_h, 384, 384);

    // W-direction
    gemm_mma_t<false><<<ggen, 256, GEMM_SMEM_BYTES>>>(p_vw, 64, p_wgr + 65536, 64, bg_w, p_lg, 1024, 64);
    mixapply_kernel<<<2048, 256, MA_SMEM_BYTES>>>(x, p_lg, p_mid, 1);
    gemm_mma_t<false><<<ggemm, 256, GEMM_SMEM_BYTES>>>(p_mid, 384, p_wr + 147456, 384, bo_w, p_w, 384, 384);

    // channel path (raw x -> inline cvt)
    gemm_mma_t<true><<<ggemm, 256, GEMM_SMEM_BYTES>>>(x, 384, Wmlpc, 384, nullptr, p_c, 384, 384);

    // pool + MLP + blend
    pool1_kernel<<<dim3(64, 16), 384>>>(p_h, p_w, p_c, p_part);
    mlp_kernel<<<64, 384>>>(p_part, Wr1, br1, Wr2, br2, p_a);
    blend_kernel<<<(NTOK / 4 + 255) / 256, 256>>>(p_h, p_w, p_c, p_a);

    // final projection
    gemm_mma_t<false><<<ggemm, 256, GEMM_SMEM_BYTES>>>(p_c, 384, p_wr + 2 * 147456, 384, bp, out, 384, 384);
}

// round 7
// speedup vs baseline: 4.3541x; 1.6022x over previous
#include <cuda_runtime.h>
#include <cuda_bf16.h>
#include <math.h>
#include <stdint.h>

// ---------------------------------------------------------------------------
// Problem constants: B=64, RES=32, DIM=384, NH=8, RD=2
// ---------------------------------------------------------------------------
#define NTOK   25165824   // 64*32*32*384
#define NROWS  65536
#define CDIM   384

// Scratch (device globals; allocation-free)
__device__ float g_mid[NTOK];
__device__ float g_h[NTOK];
__device__ float g_w[NTOK];
__device__ float g_c[NTOK];
__device__ float g_part[64 * 16 * 384];
__device__ float g_a[3 * 64 * 384];
__device__ float g_vh[2048 * 8 * 64];
__device__ float g_vw[2048 * 8 * 64];
__device__ float g_logits[16384 * 1024];
__device__ float g_wr[3 * 147456];   // rounded Wo_h | Wo_w | Wp
__device__ float g_wgr[2 * 65536];   // rounded Wg_h | Wg_w

__device__ __forceinline__ float tf32_rna(float x) {
    uint32_t u;
    asm("cvt.rna.tf32.f32 %0, %1;" : "=r"(u) : "f"(x));
    return __uint_as_float(u);
}
__device__ __forceinline__ uint32_t tf32_rna_u(float x) {
    uint32_t u;
    asm("cvt.rna.tf32.f32 %0, %1;" : "=r"(u) : "f"(x));
    return u;
}

__device__ __forceinline__ uint32_t smem_u32(const void* p) {
    uint32_t a;
    asm("{ .reg .u64 t; cvta.to.shared.u64 t, %1; cvt.u32.u64 %0, t; }"
        : "=r"(a) : "l"(p));
    return a;
}

__device__ __forceinline__ void cp_async16(uint32_t dst, const void* src) {
    asm volatile("cp.async.ca.shared.global [%0], [%1], 16;"
                 :: "r"(dst), "l"(src));
}
__device__ __forceinline__ void cp_commit() {
    asm volatile("cp.async.commit_group;");
}
template <int N>
__device__ __forceinline__ void cp_wait() {
    asm volatile("cp.async.wait_group %0;" :: "n"(N));
}

__device__ __forceinline__ void mma_tf32(float* d, const uint32_t* a, const uint32_t* b) {
    asm volatile(
        "mma.sync.aligned.m16n8k8.row.col.f32.tf32.tf32.f32 "
        "{%0,%1,%2,%3}, {%4,%5,%6,%7}, {%8,%9}, {%0,%1,%2,%3};"
        : "+f"(d[0]), "+f"(d[1]), "+f"(d[2]), "+f"(d[3])
        : "r"(a[0]), "r"(a[1]), "r"(a[2]), "r"(a[3]), "r"(b[0]), "r"(b[1]));
}

// ===========================================================================
// tf32 rounding copy kernels (weights; one-time)
// ===========================================================================
__global__ __launch_bounds__(256) void round3_kernel(
    const float* __restrict__ a, const float* __restrict__ b,
    const float* __restrict__ c, float* __restrict__ dst)
{
    const int seg = blockIdx.y;
    const float* src = seg == 0 ? a : (seg == 1 ? b : c);
    const int i = blockIdx.x * 256 + threadIdx.x;
    if (i >= 36864) return;
    float4 v = *(const float4*)(src + i * 4);
    v.x = tf32_rna(v.x); v.y = tf32_rna(v.y);
    v.z = tf32_rna(v.z); v.w = tf32_rna(v.w);
    *(float4*)(dst + seg * 147456 + i * 4) = v;
}

__global__ __launch_bounds__(256) void round2_kernel(
    const float* __restrict__ a, const float* __restrict__ b,
    float* __restrict__ dst)
{
    const int seg = blockIdx.y;
    const float* src = seg == 0 ? a : b;
    const int i = blockIdx.x * 256 + threadIdx.x;
    if (i >= 16384) return;
    float4 v = *(const float4*)(src + i * 4);
    v.x = tf32_rna(v.x); v.y = tf32_rna(v.y);
    v.z = tf32_rna(v.z); v.w = tf32_rna(v.w);
    *(float4*)(dst + seg * 65536 + i * 4) = v;
}

// ===========================================================================
// Generic tensor-core tf32 GEMM (NT), cp.async double-buffered.
// ===========================================================================
#define ASTRIDE 36
#define STAGE_F (128 * ASTRIDE)
#define GEMM_SMEM_BYTES (4 * STAGE_F * 4)

template <bool CVT>
__global__ __launch_bounds__(256, 2) void gemm_mma_t(
    const float* __restrict__ A, int lda,
    const float* __restrict__ W, int ldw,
    const float* __restrict__ bias,
    float* __restrict__ C, int ldc, int K)
{
    extern __shared__ float smg[];

    const int tid  = threadIdx.x;
    const int lane = tid & 31;
    const int wid  = tid >> 5;
    const int gID  = lane >> 2;
    const int tig  = lane & 3;
    const int wm   = (wid >> 2) * 64;
    const int wn   = (wid & 3) * 32;

    const long rowBase = (long)blockIdx.y * 128;
    const int  colBase = blockIdx.x * 128;
    const float* Abase = A + rowBase * lda;
    const float* Wbase = W + (long)colBase * ldw;

    const uint32_t smem_base = smem_u32(smg);

    float acc[4][4][4];
#pragma unroll
    for (int i = 0; i < 4; i++)
#pragma unroll
        for (int j = 0; j < 4; j++)
#pragma unroll
            for (int r = 0; r < 4; r++) acc[i][j][r] = 0.f;

    const int nk = K >> 5;

    {
#pragma unroll
        for (int s = 0; s < 4; s++) {
            const int idx = tid + s * 256;
            const int r = idx >> 3;
            const int g = (idx & 7) * 4;
            const uint32_t soff = (uint32_t)(r * ASTRIDE + g) * 4u;
            cp_async16(smem_base + soff, Abase + (long)r * lda + g);
            cp_async16(smem_base + (uint32_t)STAGE_F * 4u + soff,
                       Wbase + (long)r * ldw + g);
        }
        cp_commit();
    }

#pragma unroll 1
    for (int kti = 0; kti < nk; kti++) {
        const int st = kti & 1;
        if (kti + 1 < nk) {
            const int kt = (kti + 1) << 5;
            const uint32_t stoff = (uint32_t)((st ^ 1) * 2 * STAGE_F) * 4u;
#pragma unroll
            for (int s = 0; s < 4; s++) {
                const int idx = tid + s * 256;
                const int r = idx >> 3;
                const int g = (idx & 7) * 4;
                const uint32_t soff = (uint32_t)(r * ASTRIDE + g) * 4u;
                cp_async16(smem_base + stoff + soff,
                           Abase + (long)r * lda + kt + g);
                cp_async16(smem_base + stoff + (uint32_t)STAGE_F * 4u + soff,
                           Wbase + (long)r * ldw + kt + g);
            }
            cp_commit();
            cp_wait<1>();
        } else {
            cp_wait<0>();
        }
        __syncthreads();

        const float* As = smg + st * 2 * STAGE_F;
        const float* Ws = As + STAGE_F;

#pragma unroll
        for (int kk = 0; kk < 32; kk += 8) {
            uint32_t af[4][4], bf[4][2];
#pragma unroll
            for (int mt = 0; mt < 4; mt++) {
                const int row0 = wm + mt * 16 + gID;
                if (CVT) {
                    af[mt][0] = tf32_rna_u(As[row0 * ASTRIDE + kk + tig]);
                    af[mt][1] = tf32_rna_u(As[(row0 + 8) * ASTRIDE + kk + tig]);
                    af[mt][2] = tf32_rna_u(As[row0 * ASTRIDE + kk + tig + 4]);
                    af[mt][3] = tf32_rna_u(As[(row0 + 8) * ASTRIDE + kk + tig + 4]);
                } else {
                    af[mt][0] = __float_as_uint(As[row0 * ASTRIDE + kk + tig]);
                    af[mt][1] = __float_as_uint(As[(row0 + 8) * ASTRIDE + kk + tig]);
                    af[mt][2] = __float_as_uint(As[row0 * ASTRIDE + kk + tig + 4]);
                    af[mt][3] = __float_as_uint(As[(row0 + 8) * ASTRIDE + kk + tig + 4]);
                }
            }
#pragma unroll
            for (int nt = 0; nt < 4; nt++) {
                const int col0 = wn + nt * 8 + gID;
                if (CVT) {
                    bf[nt][0] = tf32_rna_u(Ws[col0 * ASTRIDE + kk + tig]);
                    bf[nt][1] = tf32_rna_u(Ws[col0 * ASTRIDE + kk + tig + 4]);
                } else {
                    bf[nt][0] = __float_as_uint(Ws[col0 * ASTRIDE + kk + tig]);
                    bf[nt][1] = __float_as_uint(Ws[col0 * ASTRIDE + kk + tig + 4]);
                }
            }
#pragma unroll
            for (int mt = 0; mt < 4; mt++)
#pragma unroll
                for (int nt = 0; nt < 4; nt++)
                    mma_tf32(acc[mt][nt], af[mt], bf[nt]);
        }
        __syncthreads();
    }

#pragma unroll
    for (int mt = 0; mt < 4; mt++) {
        const long row0 = rowBase + wm + mt * 16 + gID;
#pragma unroll
        for (int nt = 0; nt < 4; nt++) {
            const int col = colBase + wn + nt * 8 + tig * 2;
            float bx = 0.f, by = 0.f;
            if (bias) { bx = bias[col]; by = bias[col + 1]; }
            *(float2*)(C + row0 * ldc + col) =
                make_float2(acc[mt][nt][0] + bx, acc[mt][nt][1] + by);
            *(float2*)(C + (row0 + 8) * ldc + col) =
                make_float2(acc[mt][nt][2] + bx, acc[mt][nt][3] + by);
        }
    }
}

// ===========================================================================
// Compress (both directions in one x pass), 2x2 register blocking,
// weights staged in smem with conflict-free padded strides.
// smem: xs[32][392] + wcs[2*16][388]  (~99.8 KB)
// ===========================================================================
#define XS_STR 392
#define WC_STR 388
#define CMP_SMEM_BYTES ((32 * XS_STR + 32 * WC_STR) * 4)

__global__ __launch_bounds__(256) void compress_kernel(
    const float* __restrict__ x,
    const float* __restrict__ WcH, const float* __restrict__ bcH,
    const float* __restrict__ WcW, const float* __restrict__ bcW,
    float* __restrict__ vh, float* __restrict__ vw)
{
    extern __shared__ float sm[];
    float* xs  = sm;                    // [32][392]
    float* wcs = sm + 32 * XS_STR;      // [2*16][388]

    const int blk = blockIdx.x;
    const int b = blk >> 5;
    const int hrow = blk & 31;
    const long t0 = (long)blk * 32;
    const int tid = threadIdx.x;

    // stage x rows (float4)
    for (int i = tid; i < 3072; i += 256) {
        const int r = i / 96;
        const int c4 = i - r * 96;
        *(float4*)&xs[r * XS_STR + c4 * 4] =
            *(const float4*)&x[t0 * 384 + (long)i * 4];
    }
    // stage weights: rows 0..15 WcH, 16..31 WcW
    for (int i = tid; i < 3072; i += 256) {
        const int r = i / 96;            // 0..31
        const int c4 = i - r * 96;
        const float4 v = (r < 16)
            ? *(const float4*)&WcH[r * 384 + c4 * 4]
            : *(const float4*)&WcW[(r - 16) * 384 + c4 * 4];
        *(float4*)&wcs[r * WC_STR + c4 * 4] = v;
    }
    __syncthreads();

    // thread -> (dirW, l pair, o pair)
    const int dirW = tid >> 7;           // 0/1
    const int lp = (tid >> 3) & 15;      // 0..15
    const int op = tid & 7;              // 0..7
    const int l0 = lp * 2;
    const int o0 = op * 2;
    const float* xr0 = &xs[l0 * XS_STR];
    const float* xr1 = &xs[(l0 + 1) * XS_STR];
    const float* wr0 = &wcs[(dirW * 16 + o0) * WC_STR];
    const float* wr1 = &wcs[(dirW * 16 + o0 + 1) * WC_STR];

    float s00 = 0.f, s01 = 0.f, s10 = 0.f, s11 = 0.f;
#pragma unroll 4
    for (int c4 = 0; c4 < 96; c4++) {
        const float4 x0 = *(const float4*)&xr0[c4 * 4];
        const float4 x1 = *(const float4*)&xr1[c4 * 4];
        const float4 w0 = *(const float4*)&wr0[c4 * 4];
        const float4 w1 = *(const float4*)&wr1[c4 * 4];
        s00 += x0.x * w0.x + x0.y * w0.y + x0.z * w0.z + x0.w * w0.w;
        s01 += x0.x * w1.x + x0.y * w1.y + x0.z * w1.z + x0.w * w1.w;
        s10 += x1.x * w0.x + x1.y * w0.y + x1.z * w0.z + x1.w * w0.w;
        s11 += x1.x * w1.x + x1.y * w1.y + x1.z * w1.z + x1.w * w1.w;
    }

    const float* bc = dirW ? bcW : bcH;
    float r00 = tf32_rna(s00 + bc[o0]);
    float r01 = tf32_rna(s01 + bc[o0 + 1]);
    float r10 = tf32_rna(s10 + bc[o0]);
    float r11 = tf32_rna(s11 + bc[o0 + 1]);

    // scatter: h = o>>1, r = o&1 ; o0 even -> o0: (h0, r0=0), o0+1: (h0, r1=1)
    const int h0 = o0 >> 1;
    if (dirW) {
        const int n = b * 32 + hrow;
        float* dst = &vw[(n * 8 + h0) * 64];
        dst[l0 * 2 + 0] = r00;
        dst[l0 * 2 + 1] = r01;
        dst[(l0 + 1) * 2 + 0] = r10;
        dst[(l0 + 1) * 2 + 1] = r11;
    } else {
        // n depends on l
        vh[((b * 32 + l0) * 8 + h0) * 64 + hrow * 2 + 0] = r00;
        vh[((b * 32 + l0) * 8 + h0) * 64 + hrow * 2 + 1] = r01;
        vh[((b * 32 + l0 + 1) * 8 + h0) * 64 + hrow * 2 + 0] = r10;
        vh[((b * 32 + l0 + 1) * 8 + h0) * 64 + hrow * 2 + 1] = r11;
    }
}

// ===========================================================================
// Softmax + apply per sequence; phase 4 uses 4-way j register blocking.
// ===========================================================================
#define MA_SMEM_BYTES ((9216 + 12288) * 4)
#define SMW(h, l, j) smw[(h) * 1152 + (l) * 36 + (j)]

__global__ __launch_bounds__(256) void mixapply_kernel(
    const float* __restrict__ x,
    const float* __restrict__ logits,
    float* __restrict__ out,
    int dir)
{
    extern __shared__ float sm[];
    float* smw = sm;            // [8][32][36]
    float* xs  = sm + 9216;     // [32][384]

    const int n = blockIdx.x;
    const int b = n >> 5;
    const int q = n & 31;
    long base;
    int stride;
    if (dir == 0) { base = ((long)b * 1024 + q) * 384; stride = 32 * 384; }
    else          { base = ((long)(b * 32 + q)) * 32 * 384; stride = 384; }

    const int tid = threadIdx.x;

    for (int i = tid; i < 3072; i += 256) {
        const int r = i / 96;
        const int c4 = i - r * 96;
        *(float4*)&xs[r * 384 + c4 * 4] =
            *(const float4*)&x[base + (long)r * stride + c4 * 4];
    }
    const float4* lg = (const float4*)&logits[(long)n * 8192];
    for (int i = tid; i < 2048; i += 256) {
        const int h = i >> 8;
        const int m4 = i & 255;
        const int l = m4 >> 3;
        const int j = (m4 & 7) * 4;
        *(float4*)&SMW(h, l, j) = lg[i];
    }
    __syncthreads();

    // softmax over l for each (h, j)
    {
        const int h = tid >> 5;
        const int j = tid & 31;
        float mx = -1e30f;
#pragma unroll
        for (int l = 0; l < 32; l++) mx = fmaxf(mx, SMW(h, l, j));
        float sum = 0.f;
#pragma unroll
        for (int l = 0; l < 32; l++) {
            float e = __expf(SMW(h, l, j) - mx);
            SMW(h, l, j) = e;
            sum += e;
        }
        float inv = 1.f / sum;
#pragma unroll
        for (int l = 0; l < 32; l++) SMW(h, l, j) *= inv;
    }
    __syncthreads();

    // apply with 4-way j blocking: 768 items = (jb 0..7) x (c4 0..95)
    for (int it = tid; it < 768; it += 256) {
        const int jb = it / 96;
        const int c4 = it - jb * 96;
        const int h  = c4 / 12;
        const int j0 = jb * 4;
        float4 a0 = make_float4(0.f, 0.f, 0.f, 0.f);
        float4 a1 = a0, a2 = a0, a3 = a0;
#pragma unroll
        for (int l = 0; l < 32; l++) {
            const float4 xv = *(const float4*)&xs[l * 384 + c4 * 4];
            const float4 wv = *(const float4*)&SMW(h, l, j0);
            a0.x += xv.x * wv.x; a0.y += xv.y * wv.x;
            a0.z += xv.z * wv.x; a0.w += xv.w * wv.x;
            a1.x += xv.x * wv.y; a1.y += xv.y * wv.y;
            a1.z += xv.z * wv.y; a1.w += xv.w * wv.y;
            a2.x += xv.x * wv.z; a2.y += xv.y * wv.z;
            a2.z += xv.z * wv.z; a2.w += xv.w * wv.z;
            a3.x += xv.x * wv.w; a3.y += xv.y * wv.w;
            a3.z += xv.z * wv.w; a3.w += xv.w * wv.w;
        }
        a0.x = tf32_rna(a0.x); a0.y = tf32_rna(a0.y);
        a0.z = tf32_rna(a0.z); a0.w = tf32_rna(a0.w);
        a1.x = tf32_rna(a1.x); a1.y = tf32_rna(a1.y);
        a1.z = tf32_rna(a1.z); a1.w = tf32_rna(a1.w);
        a2.x = tf32_rna(a2.x); a2.y = tf32_rna(a2.y);
        a2.z = tf32_rna(a2.z); a2.w = tf32_rna(a2.w);
        a3.x = tf32_rna(a3.x); a3.y = tf32_rna(a3.y);
        a3.z = tf32_rna(a3.z); a3.w = tf32_rna(a3.w);
        float* o0 = &out[base + (long)(j0 + 0) * stride + c4 * 4];
        float* o1 = &out[base + (long)(j0 + 1) * stride + c4 * 4];
        float* o2 = &out[base + (long)(j0 + 2) * stride + c4 * 4];
        float* o3 = &out[base + (long)(j0 + 3) * stride + c4 * 4];
        *(float4*)o0 = a0;
        *(float4*)o1 = a1;
        *(float4*)o2 = a2;
        *(float4*)o3 = a3;
    }
}
#undef SMW

// ===========================================================================
// Pool stage 1
// ===========================================================================
__global__ __launch_bounds__(384) void pool1_kernel(
    const float* __restrict__ h,
    const float* __restrict__ w,
    const float* __restrict__ c,
    float* __restrict__ part)
{
    const int b = blockIdx.x;
    const int ch = blockIdx.y;
    const int t = threadIdx.x;
    long base = ((long)b * 1024 + ch * 64) * 384 + t;
    float s = 0.f;
#pragma unroll 8
    for (int p = 0; p < 64; p++) {
        long o = base + (long)p * 384;
        s += h[o] + w[o] + c[o];
    }
    part[(b * 16 + ch) * 384 + t] = s;
}

// ===========================================================================
// Reweighting MLP + 3-way softmax
// ===========================================================================
__global__ __launch_bounds__(384) void mlp_kernel(
    const float* __restrict__ part,
    const float* __restrict__ Wr1, const float* __restrict__ br1,
    const float* __restrict__ Wr2, const float* __restrict__ br2,
    float* __restrict__ ga)
{
    __shared__ float pool_s[384];
    __shared__ float a1_s[96];
    const int b = blockIdx.x;
    const int t = threadIdx.x;

    float s = 0.f;
#pragma unroll
    for (int ch = 0; ch < 16; ch++) s += part[(b * 16 + ch) * 384 + t];
    pool_s[t] = s * (1.f / 1024.f);
    __syncthreads();

    if (t < 96) {
        float acc = br1[t];
        const float* wr = &Wr1[t * 384];
#pragma unroll 8
        for (int c = 0; c < 384; c++) acc += pool_s[c] * wr[c];
        a1_s[t] = 0.5f * acc * (1.f + erff(acc * 0.70710678118654752f));
    }
    __syncthreads();

    float v[3];
#pragma unroll
    for (int k = 0; k < 3; k++) {
        const int o = t * 3 + k;
        float acc = br2[o];
        const float* wr = &Wr2[o * 96];
#pragma unroll 8
        for (int i = 0; i < 96; i++) acc += a1_s[i] * wr[i];
        v[k] = acc;
    }
    float mx = fmaxf(v[0], fmaxf(v[1], v[2]));
    float e0 = __expf(v[0] - mx);
    float e1 = __expf(v[1] - mx);
    float e2 = __expf(v[2] - mx);
    float inv = 1.f / (e0 + e1 + e2);
    ga[(0 * 64 + b) * 384 + t] = e0 * inv;
    ga[(1 * 64 + b) * 384 + t] = e1 * inv;
    ga[(2 * 64 + b) * 384 + t] = e2 * inv;
}

// ===========================================================================
// Blend (in place into c); output pre-rounded to tf32.
// ===========================================================================
__global__ __launch_bounds__(256) void blend_kernel(
    const float* __restrict__ h,
    const float* __restrict__ w,
    float* __restrict__ c,
    const float* __restrict__ ga)
{
    const long i4 = (long)blockIdx.x * blockDim.x + threadIdx.x;
    if (i4 >= (NTOK / 4)) return;
    const long e = i4 * 4;
    const int b = (int)(e / (1024 * 384));
    const int ci = (int)(e % 384);

    float4 h4 = *(const float4*)&h[e];
    float4 w4 = *(const float4*)&w[e];
    float4 c4 = *(const float4*)&c[e];
    float4 a0 = *(const float4*)&ga[(0 * 64 + b) * 384 + ci];
    float4 a1 = *(const float4*)&ga[(1 * 64 + b) * 384 + ci];
    float4 a2 = *(const float4*)&ga[(2 * 64 + b) * 384 + ci];
    float4 r;
    r.x = tf32_rna(h4.x * a0.x + w4.x * a1.x + c4.x * a2.x);
    r.y = tf32_rna(h4.y * a0.y + w4.y * a1.y + c4.y * a2.y);
    r.z = tf32_rna(h4.z * a0.z + w4.z * a1.z + c4.z * a2.z);
    r.w = tf32_rna(h4.w * a0.w + w4.w * a1.w + c4.w * a2.w);
    *(float4*)&c[e] = r;
}

// ===========================================================================
// Launch
// ===========================================================================
extern "C" void kernel_launch(void* const* d_in, const int* in_sizes, int n_in,
                              void* d_out, int out_size)
{
    const float* x     = (const float*)d_in[0];
    const float* Wc_h  = (const float*)d_in[1];
    const float* bc_h  = (const float*)d_in[2];
    const float* Wg_h  = (const float*)d_in[3];
    const float* bg_h  = (const float*)d_in[4];
    const float* Wo_h  = (const float*)d_in[5];
    const float* bo_h  = (const float*)d_in[6];
    const float* Wc_w  = (const float*)d_in[7];
    const float* bc_w  = (const float*)d_in[8];
    const float* Wg_w  = (const float*)d_in[9];
    const float* bg_w  = (const float*)d_in[10];
    const float* Wo_w  = (const float*)d_in[11];
    const float* bo_w  = (const float*)d_in[12];
    const float* Wmlpc = (const float*)d_in[13];
    const float* Wr1   = (const float*)d_in[14];
    const float* br1   = (const float*)d_in[15];
    const float* Wr2   = (const float*)d_in[16];
    const float* br2   = (const float*)d_in[17];
    const float* Wp    = (const float*)d_in[18];
    const float* bp    = (const float*)d_in[19];
    float* out = (float*)d_out;

    float *p_mid, *p_h, *p_w, *p_c, *p_part, *p_a, *p_vh, *p_vw, *p_lg, *p_wr, *p_wgr;
    cudaGetSymbolAddress((void**)&p_mid,  g_mid);
    cudaGetSymbolAddress((void**)&p_h,    g_h);
    cudaGetSymbolAddress((void**)&p_w,    g_w);
    cudaGetSymbolAddress((void**)&p_c,    g_c);
    cudaGetSymbolAddress((void**)&p_part, g_part);
    cudaGetSymbolAddress((void**)&p_a,    g_a);
    cudaGetSymbolAddress((void**)&p_vh,   g_vh);
    cudaGetSymbolAddress((void**)&p_vw,   g_vw);
    cudaGetSymbolAddress((void**)&p_lg,   g_logits);
    cudaGetSymbolAddress((void**)&p_wr,   g_wr);
    cudaGetSymbolAddress((void**)&p_wgr,  g_wgr);

    cudaFuncSetAttribute(gemm_mma_t<false>,
                         cudaFuncAttributeMaxDynamicSharedMemorySize, GEMM_SMEM_BYTES);
    cudaFuncSetAttribute(gemm_mma_t<true>,
                         cudaFuncAttributeMaxDynamicSharedMemorySize, GEMM_SMEM_BYTES);
    cudaFuncSetAttribute(compress_kernel,
                         cudaFuncAttributeMaxDynamicSharedMemorySize, CMP_SMEM_BYTES);
    cudaFuncSetAttribute(mixapply_kernel,
                         cudaFuncAttributeMaxDynamicSharedMemorySize, MA_SMEM_BYTES);

    dim3 ggemm(3, NROWS / 128);
    dim3 ggen(8, 128);

    // one-time weight rounding
    round3_kernel<<<dim3(144, 3), 256>>>(Wo_h, Wo_w, Wp, p_wr);
    round2_kernel<<<dim3(64, 2), 256>>>(Wg_h, Wg_w, p_wgr);

    compress_kernel<<<2048, 256, CMP_SMEM_BYTES>>>(x, Wc_h, bc_h, Wc_w, bc_w, p_vh, p_vw);

    // H-direction
    gemm_mma_t<false><<<ggen, 256, GEMM_SMEM_BYTES>>>(p_vh, 64, p_wgr, 64, bg_h, p_lg, 1024, 64);
    mixapply_kernel<<<2048, 256, MA_SMEM_BYTES>>>(x, p_lg, p_mid, 0);
    gemm_mma_t<false><<<ggemm, 256, GEMM_SMEM_BYTES>>>(p_mid, 384, p_wr, 384, bo_h, p_h, 384, 384);

    // W-direction
    gemm_mma_t<false><<<ggen, 256, GEMM_SMEM_BYTES>>>(p_vw, 64, p_wgr + 65536, 64, bg_w, p_lg, 1024, 64);
    mixapply_kernel<<<2048, 256, MA_SMEM_BYTES>>>(x, p_lg, p_mid, 1);
    gemm_mma_t<false><<<ggemm, 256, GEMM_SMEM_BYTES>>>(p_mid, 384, p_wr + 147456, 384, bo_w, p_w, 384, 384);

    // channel path (raw x -> inline cvt)
    gemm_mma_t<true><<<ggemm, 256, GEMM_SMEM_BYTES>>>(x, 384, Wmlpc, 384, nullptr, p_c, 384, 384);

    // pool + MLP + blend
    pool1_kernel<<<dim3(64, 16), 384>>>(p_h, p_w, p_c, p_part);
    mlp_kernel<<<64, 384>>>(p_part, Wr1, br1, Wr2, br2, p_a);
    blend_kernel<<<(NTOK / 4 + 255) / 256, 256>>>(p_h, p_w, p_c, p_a);

    // final projection
    gemm_mma_t<false><<<ggemm, 256, GEMM_SMEM_BYTES>>>(p_c, 384, p_wr + 2 * 147456, 384, bp, out, 384, 384);
}

// round 8
// speedup vs baseline: 5.3097x; 1.2195x over previous
#include <cuda_runtime.h>
#include <cuda_fp16.h>
#include <math.h>
#include <stdint.h>

// ---------------------------------------------------------------------------
// Problem constants: B=64, RES=32, DIM=384, NH=8, RD=2
// ---------------------------------------------------------------------------
#define NTOK   25165824   // 64*32*32*384
#define NROWS  65536
#define CDIM   384

// Scratch (device globals; allocation-free)
__device__ float  g_h[NTOK];
__device__ float  g_w[NTOK];
__device__ float  g_c[NTOK];
__device__ float  g_part[64 * 16 * 384];
__device__ float  g_a[3 * 64 * 384];
__device__ float  g_logits[16384 * 1024];
__device__ __half g_xh[NTOK];
__device__ __half g_midh[NTOK];
__device__ __half g_cbh[NTOK];
__device__ __half g_vhh[2048 * 8 * 64];
__device__ __half g_vwh[2048 * 8 * 64];
__device__ __half g_whr[4 * 147456];  // half: Wo_h | Wo_w | Wp | Wmlpc
__device__ __half g_wgh[2 * 65536];   // half: Wg_h | Wg_w

__device__ __forceinline__ uint32_t smem_u32(const void* p) {
    uint32_t a;
    asm("{ .reg .u64 t; cvta.to.shared.u64 t, %1; cvt.u32.u64 %0, t; }"
        : "=r"(a) : "l"(p));
    return a;
}

__device__ __forceinline__ void cp_async16(uint32_t dst, const void* src) {
    asm volatile("cp.async.ca.shared.global [%0], [%1], 16;"
                 :: "r"(dst), "l"(src));
}
__device__ __forceinline__ void cp_commit() {
    asm volatile("cp.async.commit_group;");
}
template <int N>
__device__ __forceinline__ void cp_wait() {
    asm volatile("cp.async.wait_group %0;" :: "n"(N));
}

__device__ __forceinline__ void mma_f16(float* d, const uint32_t* a, const uint32_t* b) {
    asm volatile(
        "mma.sync.aligned.m16n8k16.row.col.f32.f16.f16.f32 "
        "{%0,%1,%2,%3}, {%4,%5,%6,%7}, {%8,%9}, {%0,%1,%2,%3};"
        : "+f"(d[0]), "+f"(d[1]), "+f"(d[2]), "+f"(d[3])
        : "r"(a[0]), "r"(a[1]), "r"(a[2]), "r"(a[3]), "r"(b[0]), "r"(b[1]));
}

__device__ __forceinline__ uint32_t pack_h2(float lo, float hi) {
    __half2 h = __floats2half2_rn(lo, hi);
    return *(uint32_t*)&h;
}

// ===========================================================================
// f32 -> f16 conversion kernels (weights one-time; x once per call)
// ===========================================================================
__global__ __launch_bounds__(256) void round4h_kernel(
    const float* __restrict__ a, const float* __restrict__ b,
    const float* __restrict__ c, const float* __restrict__ d,
    __half* __restrict__ dst)
{
    const int seg = blockIdx.y;
    const float* src = seg == 0 ? a : (seg == 1 ? b : (seg == 2 ? c : d));
    const int i = blockIdx.x * 256 + threadIdx.x;     // float4 idx, 36864/seg
    if (i >= 36864) return;
    float4 v = *(const float4*)(src + i * 4);
    uint2 u;
    u.x = pack_h2(v.x, v.y);
    u.y = pack_h2(v.z, v.w);
    *(uint2*)(dst + seg * 147456 + i * 4) = u;
}

__global__ __launch_bounds__(256) void round2h_kernel(
    const float* __restrict__ a, const float* __restrict__ b,
    __half* __restrict__ dst)
{
    const int seg = blockIdx.y;
    const float* src = seg == 0 ? a : b;
    const int i = blockIdx.x * 256 + threadIdx.x;     // float4 idx, 16384/seg
    if (i >= 16384) return;
    float4 v = *(const float4*)(src + i * 4);
    uint2 u;
    u.x = pack_h2(v.x, v.y);
    u.y = pack_h2(v.z, v.w);
    *(uint2*)(dst + seg * 65536 + i * 4) = u;
}

__global__ __launch_bounds__(256) void f2h_kernel(
    const float* __restrict__ src, __half* __restrict__ dst)
{
    const long i = (long)blockIdx.x * 256 + threadIdx.x;   // 8 floats each
    float4 a = *(const float4*)(src + i * 8);
    float4 b = *(const float4*)(src + i * 8 + 4);
    uint4 u;
    u.x = pack_h2(a.x, a.y);
    u.y = pack_h2(a.z, a.w);
    u.z = pack_h2(b.x, b.y);
    u.w = pack_h2(b.z, b.w);
    *(uint4*)(dst + i * 8) = u;
}

// ===========================================================================
// fp16 tensor-core GEMM (NT), cp.async double-buffered.
// C[M,N] = A[M,K] * W[N,K]^T (+bias), A/W f16, C f32.
// Block tile 128x128, BK=64, 256 threads / 8 warps (2x4), warp tile 64x32.
// Grid (N/128, M/128). Requires M%128==0, N%128==0, K%64==0, lda/ldw %8==0.
// smem: 2 stages x 2 operands x 128 rows x 72 halves = 73728 B.
// ===========================================================================
#define HS2 36                      // uint32 (half2) stride per row
#define HSTAGE_U32 (128 * HS2)      // 4608 uint32 per operand stage
#define GEMM_SMEM_BYTES (4 * HSTAGE_U32 * 4)

__global__ __launch_bounds__(256, 2) void gemm_h(
    const __half* __restrict__ A, int lda,
    const __half* __restrict__ W, int ldw,
    const float* __restrict__ bias,   // may be null
    float* __restrict__ C, int ldc, int K)
{
    extern __shared__ uint32_t smh[];

    const int tid  = threadIdx.x;
    const int lane = tid & 31;
    const int wid  = tid >> 5;
    const int gID  = lane >> 2;
    const int tig  = lane & 3;
    const int wm   = (wid >> 2) * 64;
    const int wn   = (wid & 3) * 32;

    const long rowBase = (long)blockIdx.y * 128;
    const int  colBase = blockIdx.x * 128;
    const __half* Abase = A + rowBase * lda;
    const __half* Wbase = W + (long)colBase * ldw;

    const uint32_t smem_base = smem_u32(smh);

    float acc[4][4][4];
#pragma unroll
    for (int i = 0; i < 4; i++)
#pragma unroll
        for (int j = 0; j < 4; j++)
#pragma unroll
            for (int r = 0; r < 4; r++) acc[i][j][r] = 0.f;

    const int nk = K >> 6;

    // prologue: tile 0 into stage 0
    {
#pragma unroll
        for (int s = 0; s < 4; s++) {
            const int idx = tid + s * 256;       // 0..1023
            const int r = idx >> 3;              // 0..127
            const int c = (idx & 7) * 8;         // half offset 0..56
            const uint32_t soff = (uint32_t)(r * 144 + c * 2);
            cp_async16(smem_base + soff, Abase + (long)r * lda + c);
            cp_async16(smem_base + (uint32_t)(HSTAGE_U32 * 4) + soff,
                       Wbase + (long)r * ldw + c);
        }
        cp_commit();
    }

#pragma unroll 1
    for (int kti = 0; kti < nk; kti++) {
        const int st = kti & 1;
        if (kti + 1 < nk) {
            const int kt = (kti + 1) << 6;
            const uint32_t stoff = (uint32_t)((st ^ 1) * 2 * HSTAGE_U32 * 4);
#pragma unroll
            for (int s = 0; s < 4; s++) {
                const int idx = tid + s * 256;
                const int r = idx >> 3;
                const int c = (idx & 7) * 8;
                const uint32_t soff = (uint32_t)(r * 144 + c * 2);
                cp_async16(smem_base + stoff + soff,
                           Abase + (long)r * lda + kt + c);
                cp_async16(smem_base + stoff + (uint32_t)(HSTAGE_U32 * 4) + soff,
                           Wbase + (long)r * ldw + kt + c);
            }
            cp_commit();
            cp_wait<1>();
        } else {
            cp_wait<0>();
        }
        __syncthreads();

        const uint32_t* As = smh + st * 2 * HSTAGE_U32;
        const uint32_t* Ws = As + HSTAGE_U32;

#pragma unroll
        for (int kk2 = 0; kk2 < 32; kk2 += 8) {   // half2 base index per k16 step
            uint32_t af[4][4], bf[4][2];
#pragma unroll
            for (int mt = 0; mt < 4; mt++) {
                const int row0 = wm + mt * 16 + gID;
                af[mt][0] = As[row0 * HS2 + kk2 + tig];
                af[mt][1] = As[(row0 + 8) * HS2 + kk2 + tig];
                af[mt][2] = As[row0 * HS2 + kk2 + tig + 4];
                af[mt][3] = As[(row0 + 8) * HS2 + kk2 + tig + 4];
            }
#pragma unroll
            for (int nt = 0; nt < 4; nt++) {
                const int col0 = wn + nt * 8 + gID;
                bf[nt][0] = Ws[col0 * HS2 + kk2 + tig];
                bf[nt][1] = Ws[col0 * HS2 + kk2 + tig + 4];
            }
#pragma unroll
            for (int mt = 0; mt < 4; mt++)
#pragma unroll
                for (int nt = 0; nt < 4; nt++)
                    mma_f16(acc[mt][nt], af[mt], bf[nt]);
        }
        __syncthreads();
    }

#pragma unroll
    for (int mt = 0; mt < 4; mt++) {
        const long row0 = rowBase + wm + mt * 16 + gID;
#pragma unroll
        for (int nt = 0; nt < 4; nt++) {
            const int col = colBase + wn + nt * 8 + tig * 2;
            float bx = 0.f, by = 0.f;
            if (bias) { bx = bias[col]; by = bias[col + 1]; }
            *(float2*)(C + row0 * ldc + col) =
                make_float2(acc[mt][nt][0] + bx, acc[mt][nt][1] + by);
            *(float2*)(C + (row0 + 8) * ldc + col) =
                make_float2(acc[mt][nt][2] + bx, acc[mt][nt][3] + by);
        }
    }
}

// ===========================================================================
// Compress (both directions in one x pass), 2x2 register blocking.
// Outputs f16.
// ===========================================================================
#define XS_STR 392
#define WC_STR 388
#define CMP_SMEM_BYTES ((32 * XS_STR + 32 * WC_STR) * 4)

__global__ __launch_bounds__(256) void compress_kernel(
    const float* __restrict__ x,
    const float* __restrict__ WcH, const float* __restrict__ bcH,
    const float* __restrict__ WcW, const float* __restrict__ bcW,
    __half* __restrict__ vh, __half* __restrict__ vw)
{
    extern __shared__ float sm[];
    float* xs  = sm;                    // [32][392]
    float* wcs = sm + 32 * XS_STR;      // [2*16][388]

    const int blk = blockIdx.x;
    const int b = blk >> 5;
    const int hrow = blk & 31;
    const long t0 = (long)blk * 32;
    const int tid = threadIdx.x;

    for (int i = tid; i < 3072; i += 256) {
        const int r = i / 96;
        const int c4 = i - r * 96;
        *(float4*)&xs[r * XS_STR + c4 * 4] =
            *(const float4*)&x[t0 * 384 + (long)i * 4];
    }
    for (int i = tid; i < 3072; i += 256) {
        const int r = i / 96;
        const int c4 = i - r * 96;
        const float4 v = (r < 16)
            ? *(const float4*)&WcH[r * 384 + c4 * 4]
            : *(const float4*)&WcW[(r - 16) * 384 + c4 * 4];
        *(float4*)&wcs[r * WC_STR + c4 * 4] = v;
    }
    __syncthreads();

    const int dirW = tid >> 7;
    const int lp = (tid >> 3) & 15;
    const int op = tid & 7;
    const int l0 = lp * 2;
    const int o0 = op * 2;
    const float* xr0 = &xs[l0 * XS_STR];
    const float* xr1 = &xs[(l0 + 1) * XS_STR];
    const float* wr0 = &wcs[(dirW * 16 + o0) * WC_STR];
    const float* wr1 = &wcs[(dirW * 16 + o0 + 1) * WC_STR];

    float s00 = 0.f, s01 = 0.f, s10 = 0.f, s11 = 0.f;
#pragma unroll 4
    for (int c4 = 0; c4 < 96; c4++) {
        const float4 x0 = *(const float4*)&xr0[c4 * 4];
        const float4 x1 = *(const float4*)&xr1[c4 * 4];
        const float4 w0 = *(const float4*)&wr0[c4 * 4];
        const float4 w1 = *(const float4*)&wr1[c4 * 4];
        s00 += x0.x * w0.x + x0.y * w0.y + x0.z * w0.z + x0.w * w0.w;
        s01 += x0.x * w1.x + x0.y * w1.y + x0.z * w1.z + x0.w * w1.w;
        s10 += x1.x * w0.x + x1.y * w0.y + x1.z * w0.z + x1.w * w0.w;
        s11 += x1.x * w1.x + x1.y * w1.y + x1.z * w1.z + x1.w * w1.w;
    }

    const float* bc = dirW ? bcW : bcH;
    __half r00 = __float2half_rn(s00 + bc[o0]);
    __half r01 = __float2half_rn(s01 + bc[o0 + 1]);
    __half r10 = __float2half_rn(s10 + bc[o0]);
    __half r11 = __float2half_rn(s11 + bc[o0 + 1]);

    const int h0 = o0 >> 1;
    if (dirW) {
        const int n = b * 32 + hrow;
        __half* dst = &vw[(n * 8 + h0) * 64];
        dst[l0 * 2 + 0] = r00;
        dst[l0 * 2 + 1] = r01;
        dst[(l0 + 1) * 2 + 0] = r10;
        dst[(l0 + 1) * 2 + 1] = r11;
    } else {
        vh[((b * 32 + l0) * 8 + h0) * 64 + hrow * 2 + 0] = r00;
        vh[((b * 32 + l0) * 8 + h0) * 64 + hrow * 2 + 1] = r01;
        vh[((b * 32 + l0 + 1) * 8 + h0) * 64 + hrow * 2 + 0] = r10;
        vh[((b * 32 + l0 + 1) * 8 + h0) * 64 + hrow * 2 + 1] = r11;
    }
}

// ===========================================================================
// Softmax + apply per sequence; 4-way j register blocking; outputs f16.
// ===========================================================================
#define MA_SMEM_BYTES ((9216 + 12288) * 4)
#define SMW(h, l, j) smw[(h) * 1152 + (l) * 36 + (j)]

__global__ __launch_bounds__(256) void mixapply_kernel(
    const float* __restrict__ x,
    const float* __restrict__ logits,
    __half* __restrict__ out,
    int dir)
{
    extern __shared__ float sm[];
    float* smw = sm;            // [8][32][36]
    float* xs  = sm + 9216;     // [32][384]

    const int n = blockIdx.x;
    const int b = n >> 5;
    const int q = n & 31;
    long base;
    int stride;
    if (dir == 0) { base = ((long)b * 1024 + q) * 384; stride = 32 * 384; }
    else          { base = ((long)(b * 32 + q)) * 32 * 384; stride = 384; }

    const int tid = threadIdx.x;

    for (int i = tid; i < 3072; i += 256) {
        const int r = i / 96;
        const int c4 = i - r * 96;
        *(float4*)&xs[r * 384 + c4 * 4] =
            *(const float4*)&x[base + (long)r * stride + c4 * 4];
    }
    const float4* lg = (const float4*)&logits[(long)n * 8192];
    for (int i = tid; i < 2048; i += 256) {
        const int h = i >> 8;
        const int m4 = i & 255;
        const int l = m4 >> 3;
        const int j = (m4 & 7) * 4;
        *(float4*)&SMW(h, l, j) = lg[i];
    }
    __syncthreads();

    {
        const int h = tid >> 5;
        const int j = tid & 31;
        float mx = -1e30f;
#pragma unroll
        for (int l = 0; l < 32; l++) mx = fmaxf(mx, SMW(h, l, j));
        float sum = 0.f;
#pragma unroll
        for (int l = 0; l < 32; l++) {
            float e = __expf(SMW(h, l, j) - mx);
            SMW(h, l, j) = e;
            sum += e;
        }
        float inv = 1.f / sum;
#pragma unroll
        for (int l = 0; l < 32; l++) SMW(h, l, j) *= inv;
    }
    __syncthreads();

    for (int it = tid; it < 768; it += 256) {
        const int jb = it / 96;
        const int c4 = it - jb * 96;
        const int h  = c4 / 12;
        const int j0 = jb * 4;
        float4 a0 = make_float4(0.f, 0.f, 0.f, 0.f);
        float4 a1 = a0, a2 = a0, a3 = a0;
#pragma unroll
        for (int l = 0; l < 32; l++) {
            const float4 xv = *(const float4*)&xs[l * 384 + c4 * 4];
            const float4 wv = *(const float4*)&SMW(h, l, j0);
            a0.x += xv.x * wv.x; a0.y += xv.y * wv.x;
            a0.z += xv.z * wv.x; a0.w += xv.w * wv.x;
            a1.x += xv.x * wv.y; a1.y += xv.y * wv.y;
            a1.z += xv.z * wv.y; a1.w += xv.w * wv.y;
            a2.x += xv.x * wv.z; a2.y += xv.y * wv.z;
            a2.z += xv.z * wv.z; a2.w += xv.w * wv.z;
            a3.x += xv.x * wv.w; a3.y += xv.y * wv.w;
            a3.z += xv.z * wv.w; a3.w += xv.w * wv.w;
        }
        uint2 u0, u1, u2, u3;
        u0.x = pack_h2(a0.x, a0.y); u0.y = pack_h2(a0.z, a0.w);
        u1.x = pack_h2(a1.x, a1.y); u1.y = pack_h2(a1.z, a1.w);
        u2.x = pack_h2(a2.x, a2.y); u2.y = pack_h2(a2.z, a2.w);
        u3.x = pack_h2(a3.x, a3.y); u3.y = pack_h2(a3.z, a3.w);
        *(uint2*)&out[base + (long)(j0 + 0) * stride + c4 * 4] = u0;
        *(uint2*)&out[base + (long)(j0 + 1) * stride + c4 * 4] = u1;
        *(uint2*)&out[base + (long)(j0 + 2) * stride + c4 * 4] = u2;
        *(uint2*)&out[base + (long)(j0 + 3) * stride + c4 * 4] = u3;
    }
}
#undef SMW

// ===========================================================================
// Pool stage 1
// ===========================================================================
__global__ __launch_bounds__(384) void pool1_kernel(
    const float* __restrict__ h,
    const float* __restrict__ w,
    const float* __restrict__ c,
    float* __restrict__ part)
{
    const int b = blockIdx.x;
    const int ch = blockIdx.y;
    const int t = threadIdx.x;
    long base = ((long)b * 1024 + ch * 64) * 384 + t;
    float s = 0.f;
#pragma unroll 8
    for (int p = 0; p < 64; p++) {
        long o = base + (long)p * 384;
        s += h[o] + w[o] + c[o];
    }
    part[(b * 16 + ch) * 384 + t] = s;
}

// ===========================================================================
// Reweighting MLP + 3-way softmax
// ===========================================================================
__global__ __launch_bounds__(384) void mlp_kernel(
    const float* __restrict__ part,
    const float* __restrict__ Wr1, const float* __restrict__ br1,
    const float* __restrict__ Wr2, const float* __restrict__ br2,
    float* __restrict__ ga)
{
    __shared__ float pool_s[384];
    __shared__ float a1_s[96];
    const int b = blockIdx.x;
    const int t = threadIdx.x;

    float s = 0.f;
#pragma unroll
    for (int ch = 0; ch < 16; ch++) s += part[(b * 16 + ch) * 384 + t];
    pool_s[t] = s * (1.f / 1024.f);
    __syncthreads();

    if (t < 96) {
        float acc = br1[t];
        const float* wr = &Wr1[t * 384];
#pragma unroll 8
        for (int c = 0; c < 384; c++) acc += pool_s[c] * wr[c];
        a1_s[t] = 0.5f * acc * (1.f + erff(acc * 0.70710678118654752f));
    }
    __syncthreads();

    float v[3];
#pragma unroll
    for (int k = 0; k < 3; k++) {
        const int o = t * 3 + k;
        float acc = br2[o];
        const float* wr = &Wr2[o * 96];
#pragma unroll 8
        for (int i = 0; i < 96; i++) acc += a1_s[i] * wr[i];
        v[k] = acc;
    }
    float mx = fmaxf(v[0], fmaxf(v[1], v[2]));
    float e0 = __expf(v[0] - mx);
    float e1 = __expf(v[1] - mx);
    float e2 = __expf(v[2] - mx);
    float inv = 1.f / (e0 + e1 + e2);
    ga[(0 * 64 + b) * 384 + t] = e0 * inv;
    ga[(1 * 64 + b) * 384 + t] = e1 * inv;
    ga[(2 * 64 + b) * 384 + t] = e2 * inv;
}

// ===========================================================================
// Blend: cb = h*a0 + w*a1 + c*a2, output f16 (feeds final GEMM).
// ===========================================================================
__global__ __launch_bounds__(256) void blend_kernel(
    const float* __restrict__ h,
    const float* __restrict__ w,
    const float* __restrict__ c,
    const float* __restrict__ ga,
    __half* __restrict__ cb)
{
    const long i4 = (long)blockIdx.x * blockDim.x + threadIdx.x;
    if (i4 >= (NTOK / 4)) return;
    const long e = i4 * 4;
    const int b = (int)(e / (1024 * 384));
    const int ci = (int)(e % 384);

    float4 h4 = *(const float4*)&h[e];
    float4 w4 = *(const float4*)&w[e];
    float4 c4 = *(const float4*)&c[e];
    float4 a0 = *(const float4*)&ga[(0 * 64 + b) * 384 + ci];
    float4 a1 = *(const float4*)&ga[(1 * 64 + b) * 384 + ci];
    float4 a2 = *(const float4*)&ga[(2 * 64 + b) * 384 + ci];
    float rx = h4.x * a0.x + w4.x * a1.x + c4.x * a2.x;
    float ry = h4.y * a0.y + w4.y * a1.y + c4.y * a2.y;
    float rz = h4.z * a0.z + w4.z * a1.z + c4.z * a2.z;
    float rw = h4.w * a0.w + w4.w * a1.w + c4.w * a2.w;
    uint2 u;
    u.x = pack_h2(rx, ry);
    u.y = pack_h2(rz, rw);
    *(uint2*)&cb[e] = u;
}

// ===========================================================================
// Launch
// ===========================================================================
extern "C" void kernel_launch(void* const* d_in, const int* in_sizes, int n_in,
                              void* d_out, int out_size)
{
    const float* x     = (const float*)d_in[0];
    const float* Wc_h  = (const float*)d_in[1];
    const float* bc_h  = (const float*)d_in[2];
    const float* Wg_h  = (const float*)d_in[3];
    const float* bg_h  = (const float*)d_in[4];
    const float* Wo_h  = (const float*)d_in[5];
    const float* bo_h  = (const float*)d_in[6];
    const float* Wc_w  = (const float*)d_in[7];
    const float* bc_w  = (const float*)d_in[8];
    const float* Wg_w  = (const float*)d_in[9];
    const float* bg_w  = (const float*)d_in[10];
    const float* Wo_w  = (const float*)d_in[11];
    const float* bo_w  = (const float*)d_in[12];
    const float* Wmlpc = (const float*)d_in[13];
    const float* Wr1   = (const float*)d_in[14];
    const float* br1   = (const float*)d_in[15];
    const float* Wr2   = (const float*)d_in[16];
    const float* br2   = (const float*)d_in[17];
    const float* Wp    = (const float*)d_in[18];
    const float* bp    = (const float*)d_in[19];
    float* out = (float*)d_out;

    float *p_h, *p_w, *p_c, *p_part, *p_a, *p_lg;
    __half *p_xh, *p_midh, *p_cbh, *p_vhh, *p_vwh, *p_whr, *p_wgh;
    cudaGetSymbolAddress((void**)&p_h,    g_h);
    cudaGetSymbolAddress((void**)&p_w,    g_w);
    cudaGetSymbolAddress((void**)&p_c,    g_c);
    cudaGetSymbolAddress((void**)&p_part, g_part);
    cudaGetSymbolAddress((void**)&p_a,    g_a);
    cudaGetSymbolAddress((void**)&p_lg,   g_logits);
    cudaGetSymbolAddress((void**)&p_xh,   g_xh);
    cudaGetSymbolAddress((void**)&p_midh, g_midh);
    cudaGetSymbolAddress((void**)&p_cbh,  g_cbh);
    cudaGetSymbolAddress((void**)&p_vhh,  g_vhh);
    cudaGetSymbolAddress((void**)&p_vwh,  g_vwh);
    cudaGetSymbolAddress((void**)&p_whr,  g_whr);
    cudaGetSymbolAddress((void**)&p_wgh,  g_wgh);

    cudaFuncSetAttribute(gemm_h,
                         cudaFuncAttributeMaxDynamicSharedMemorySize, GEMM_SMEM_BYTES);
    cudaFuncSetAttribute(compress_kernel,
                         cudaFuncAttributeMaxDynamicSharedMemorySize, CMP_SMEM_BYTES);
    cudaFuncSetAttribute(mixapply_kernel,
                         cudaFuncAttributeMaxDynamicSharedMemorySize, MA_SMEM_BYTES);

    dim3 ggemm(3, NROWS / 128);
    dim3 ggen(8, 128);

    // one-time weight conversion + x conversion
    round4h_kernel<<<dim3(144, 4), 256>>>(Wo_h, Wo_w, Wp, Wmlpc, p_whr);
    round2h_kernel<<<dim3(64, 2), 256>>>(Wg_h, Wg_w, p_wgh);
    f2h_kernel<<<NTOK / 8 / 256, 256>>>(x, p_xh);

    compress_kernel<<<2048, 256, CMP_SMEM_BYTES>>>(x, Wc_h, bc_h, Wc_w, bc_w, p_vhh, p_vwh);

    // H-direction
    gemm_h<<<ggen, 256, GEMM_SMEM_BYTES>>>(p_vhh, 64, p_wgh, 64, bg_h, p_lg, 1024, 64);
    mixapply_kernel<<<2048, 256, MA_SMEM_BYTES>>>(x, p_lg, p_midh, 0);
    gemm_h<<<ggemm, 256, GEMM_SMEM_BYTES>>>(p_midh, 384, p_whr, 384, bo_h, p_h, 384, 384);

    // W-direction
    gemm_h<<<ggen, 256, GEMM_SMEM_BYTES>>>(p_vwh, 64, p_wgh + 65536, 64, bg_w, p_lg, 1024, 64);
    mixapply_kernel<<<2048, 256, MA_SMEM_BYTES>>>(x, p_lg, p_midh, 1);
    gemm_h<<<ggemm, 256, GEMM_SMEM_BYTES>>>(p_midh, 384, p_whr + 147456, 384, bo_w, p_w, 384, 384);

    // channel path (x in f16)
    gemm_h<<<ggemm, 256, GEMM_SMEM_BYTES>>>(p_xh, 384, p_whr + 3 * 147456, 384, nullptr, p_c, 384, 384);

    // pool + MLP + blend
    pool1_kernel<<<dim3(64, 16), 384>>>(p_h, p_w, p_c, p_part);
    mlp_kernel<<<64, 384>>>(p_part, Wr1, br1, Wr2, br2, p_a);
    blend_kernel<<<(NTOK / 4 + 255) / 256, 256>>>(p_h, p_w, p_c, p_a, p_cbh);

    // final projection
    gemm_h<<<ggemm, 256, GEMM_SMEM_BYTES>>>(p_cbh, 384, p_whr + 2 * 147456, 384, bp, out, 384, 384);
}

// round 9
// speedup vs baseline: 6.8614x; 1.2922x over previous
#include <cuda_runtime.h>
#include <cuda_fp16.h>
#include <math.h>
#include <stdint.h>

// ---------------------------------------------------------------------------
// Problem constants: B=64, RES=32, DIM=384, NH=8, RD=2
// ---------------------------------------------------------------------------
#define NTOK   25165824   // 64*32*32*384
#define NROWS  65536
#define CDIM   384

// Scratch (device globals; allocation-free)
__device__ float  g_part[64 * 16 * 384];
__device__ float  g_a[3 * 64 * 384];
__device__ float  g_logits[16384 * 1024];
__device__ __half g_xh[NTOK];
__device__ __half g_midh[NTOK];
__device__ __half g_cbh[NTOK];
__device__ __half g_hh[NTOK];
__device__ __half g_wwh[NTOK];
__device__ __half g_cch[NTOK];
__device__ __half g_vhh[2048 * 8 * 64];
__device__ __half g_vwh[2048 * 8 * 64];
__device__ __half g_whr[4 * 147456];  // half: Wo_h | Wo_w | Wp | Wmlpc
__device__ __half g_wgh[2 * 65536];   // half: Wg_h | Wg_w
__device__ __half g_wcc[32 * 384];    // half: WcH rows 0-15 | WcW rows 16-31

__device__ __forceinline__ uint32_t smem_u32(const void* p) {
    uint32_t a;
    asm("{ .reg .u64 t; cvta.to.shared.u64 t, %1; cvt.u32.u64 %0, t; }"
        : "=r"(a) : "l"(p));
    return a;
}

__device__ __forceinline__ void cp_async16(uint32_t dst, const void* src) {
    asm volatile("cp.async.ca.shared.global [%0], [%1], 16;"
                 :: "r"(dst), "l"(src));
}
__device__ __forceinline__ void cp_commit() {
    asm volatile("cp.async.commit_group;");
}
template <int N>
__device__ __forceinline__ void cp_wait() {
    asm volatile("cp.async.wait_group %0;" :: "n"(N));
}

__device__ __forceinline__ void mma_f16(float* d, const uint32_t* a, const uint32_t* b) {
    asm volatile(
        "mma.sync.aligned.m16n8k16.row.col.f32.f16.f16.f32 "
        "{%0,%1,%2,%3}, {%4,%5,%6,%7}, {%8,%9}, {%0,%1,%2,%3};"
        : "+f"(d[0]), "+f"(d[1]), "+f"(d[2]), "+f"(d[3])
        : "r"(a[0]), "r"(a[1]), "r"(a[2]), "r"(a[3]), "r"(b[0]), "r"(b[1]));
}

__device__ __forceinline__ uint32_t pack_h2(float lo, float hi) {
    __half2 h = __floats2half2_rn(lo, hi);
    return *(uint32_t*)&h;
}

// ===========================================================================
// f32 -> f16 conversion kernels
// ===========================================================================
__global__ __launch_bounds__(256) void round4h_kernel(
    const float* __restrict__ a, const float* __restrict__ b,
    const float* __restrict__ c, const float* __restrict__ d,
    __half* __restrict__ dst)
{
    const int seg = blockIdx.y;
    const float* src = seg == 0 ? a : (seg == 1 ? b : (seg == 2 ? c : d));
    const int i = blockIdx.x * 256 + threadIdx.x;
    if (i >= 36864) return;
    float4 v = *(const float4*)(src + i * 4);
    uint2 u;
    u.x = pack_h2(v.x, v.y);
    u.y = pack_h2(v.z, v.w);
    *(uint2*)(dst + seg * 147456 + i * 4) = u;
}

__global__ __launch_bounds__(256) void round2h_kernel(
    const float* __restrict__ a, const float* __restrict__ b,
    __half* __restrict__ dst)
{
    const int seg = blockIdx.y;
    const float* src = seg == 0 ? a : b;
    const int i = blockIdx.x * 256 + threadIdx.x;
    if (i >= 16384) return;
    float4 v = *(const float4*)(src + i * 4);
    uint2 u;
    u.x = pack_h2(v.x, v.y);
    u.y = pack_h2(v.z, v.w);
    *(uint2*)(dst + seg * 65536 + i * 4) = u;
}

__global__ __launch_bounds__(256) void roundwc_kernel(
    const float* __restrict__ a, const float* __restrict__ b,
    __half* __restrict__ dst)
{
    const int i = blockIdx.x * 256 + threadIdx.x;   // float4 idx, 3072 total
    if (i >= 3072) return;
    const float* src = (i < 1536) ? (a + i * 4) : (b + (i - 1536) * 4);
    float4 v = *(const float4*)src;
    uint2 u;
    u.x = pack_h2(v.x, v.y);
    u.y = pack_h2(v.z, v.w);
    *(uint2*)(dst + i * 4) = u;
}

__global__ __launch_bounds__(256) void f2h_kernel(
    const float* __restrict__ src, __half* __restrict__ dst)
{
    const long i = (long)blockIdx.x * 256 + threadIdx.x;
    float4 a = *(const float4*)(src + i * 8);
    float4 b = *(const float4*)(src + i * 8 + 4);
    uint4 u;
    u.x = pack_h2(a.x, a.y);
    u.y = pack_h2(a.z, a.w);
    u.z = pack_h2(b.x, b.y);
    u.w = pack_h2(b.z, b.w);
    *(uint4*)(dst + i * 8) = u;
}

// ===========================================================================
// fp16 tensor-core GEMM (NT), cp.async double-buffered. OutT = float or half.
// Block tile 128x128, BK=64, 256 threads / 8 warps (2x4), warp tile 64x32.
// ===========================================================================
#define HS2 36
#define HSTAGE_U32 (128 * HS2)
#define GEMM_SMEM_BYTES (4 * HSTAGE_U32 * 4)

template <typename OutT>
__global__ __launch_bounds__(256, 2) void gemm_h(
    const __half* __restrict__ A, int lda,
    const __half* __restrict__ W, int ldw,
    const float* __restrict__ bias,
    OutT* __restrict__ C, int ldc, int K)
{
    extern __shared__ uint32_t smh[];

    const int tid  = threadIdx.x;
    const int lane = tid & 31;
    const int wid  = tid >> 5;
    const int gID  = lane >> 2;
    const int tig  = lane & 3;
    const int wm   = (wid >> 2) * 64;
    const int wn   = (wid & 3) * 32;

    const long rowBase = (long)blockIdx.y * 128;
    const int  colBase = blockIdx.x * 128;
    const __half* Abase = A + rowBase * lda;
    const __half* Wbase = W + (long)colBase * ldw;

    const uint32_t smem_base = smem_u32(smh);

    float acc[4][4][4];
#pragma unroll
    for (int i = 0; i < 4; i++)
#pragma unroll
        for (int j = 0; j < 4; j++)
#pragma unroll
            for (int r = 0; r < 4; r++) acc[i][j][r] = 0.f;

    const int nk = K >> 6;

    {
#pragma unroll
        for (int s = 0; s < 4; s++) {
            const int idx = tid + s * 256;
            const int r = idx >> 3;
            const int c = (idx & 7) * 8;
            const uint32_t soff = (uint32_t)(r * 144 + c * 2);
            cp_async16(smem_base + soff, Abase + (long)r * lda + c);
            cp_async16(smem_base + (uint32_t)(HSTAGE_U32 * 4) + soff,
                       Wbase + (long)r * ldw + c);
        }
        cp_commit();
    }

#pragma unroll 1
    for (int kti = 0; kti < nk; kti++) {
        const int st = kti & 1;
        if (kti + 1 < nk) {
            const int kt = (kti + 1) << 6;
            const uint32_t stoff = (uint32_t)((st ^ 1) * 2 * HSTAGE_U32 * 4);
#pragma unroll
            for (int s = 0; s < 4; s++) {
                const int idx = tid + s * 256;
                const int r = idx >> 3;
                const int c = (idx & 7) * 8;
                const uint32_t soff = (uint32_t)(r * 144 + c * 2);
                cp_async16(smem_base + stoff + soff,
                           Abase + (long)r * lda + kt + c);
                cp_async16(smem_base + stoff + (uint32_t)(HSTAGE_U32 * 4) + soff,
                           Wbase + (long)r * ldw + kt + c);
            }
            cp_commit();
            cp_wait<1>();
        } else {
            cp_wait<0>();
        }
        __syncthreads();

        const uint32_t* As = smh + st * 2 * HSTAGE_U32;
        const uint32_t* Ws = As + HSTAGE_U32;

#pragma unroll
        for (int kk2 = 0; kk2 < 32; kk2 += 8) {
            uint32_t af[4][4], bf[4][2];
#pragma unroll
            for (int mt = 0; mt < 4; mt++) {
                const int row0 = wm + mt * 16 + gID;
                af[mt][0] = As[row0 * HS2 + kk2 + tig];
                af[mt][1] = As[(row0 + 8) * HS2 + kk2 + tig];
                af[mt][2] = As[row0 * HS2 + kk2 + tig + 4];
                af[mt][3] = As[(row0 + 8) * HS2 + kk2 + tig + 4];
            }
#pragma unroll
            for (int nt = 0; nt < 4; nt++) {
                const int col0 = wn + nt * 8 + gID;
                bf[nt][0] = Ws[col0 * HS2 + kk2 + tig];
                bf[nt][1] = Ws[col0 * HS2 + kk2 + tig + 4];
            }
#pragma unroll
            for (int mt = 0; mt < 4; mt++)
#pragma unroll
                for (int nt = 0; nt < 4; nt++)
                    mma_f16(acc[mt][nt], af[mt], bf[nt]);
        }
        __syncthreads();
    }

#pragma unroll
    for (int mt = 0; mt < 4; mt++) {
        const long row0 = rowBase + wm + mt * 16 + gID;
#pragma unroll
        for (int nt = 0; nt < 4; nt++) {
            const int col = colBase + wn + nt * 8 + tig * 2;
            float bx = 0.f, by = 0.f;
            if (bias) { bx = bias[col]; by = bias[col + 1]; }
            if constexpr (sizeof(OutT) == 4) {
                *(float2*)((float*)C + row0 * ldc + col) =
                    make_float2(acc[mt][nt][0] + bx, acc[mt][nt][1] + by);
                *(float2*)((float*)C + (row0 + 8) * ldc + col) =
                    make_float2(acc[mt][nt][2] + bx, acc[mt][nt][3] + by);
            } else {
                *(uint32_t*)((__half*)C + row0 * ldc + col) =
                    pack_h2(acc[mt][nt][0] + bx, acc[mt][nt][1] + by);
                *(uint32_t*)((__half*)C + (row0 + 8) * ldc + col) =
                    pack_h2(acc[mt][nt][2] + bx, acc[mt][nt][3] + by);
            }
        }
    }
}

// ===========================================================================
// Compress as MMA GEMM: V[65536,32] = Xh[65536,384] @ Wc_both[32,384]^T,
// fused bias + scatter to vh/vw. 512 blocks x 256 threads (8 warps x 16 rows).
// smem: Bs 32x196 u32 (full K) + 2 A stages 128x36 u32 = 61952 B.
// ===========================================================================
#define CB_U32 (32 * 196)
#define CA_U32 (128 * 36)
#define CMP_SMEM_BYTES ((CB_U32 + 2 * CA_U32) * 4)

__global__ __launch_bounds__(256, 2) void compress_mma(
    const __half* __restrict__ xh,
    const __half* __restrict__ wcc,     // [32][384] half (H rows 0-15, W 16-31)
    const float* __restrict__ bcH, const float* __restrict__ bcW,
    __half* __restrict__ vh, __half* __restrict__ vw)
{
    extern __shared__ uint32_t smc[];
    uint32_t* Bs = smc;                 // [32][196]
    uint32_t* As = smc + CB_U32;        // 2 x [128][36]

    const int tid  = threadIdx.x;
    const int lane = tid & 31;
    const int wid  = tid >> 5;
    const int gID  = lane >> 2;
    const int tig  = lane & 3;
    const int wm   = wid * 16;

    const long rowBase = (long)blockIdx.x * 128;
    const __half* Abase = xh + rowBase * 384;

    const uint32_t b_base = smem_u32(Bs);
    const uint32_t a_base = smem_u32(As);

    float acc[4][4];
#pragma unroll
    for (int i = 0; i < 4; i++)
#pragma unroll
        for (int r = 0; r < 4; r++) acc[i][r] = 0.f;

    // prologue: full B + A stage 0
#pragma unroll
    for (int s = 0; s < 6; s++) {
        const int idx = tid + s * 256;      // 0..1535
        const int r = idx / 48;
        const int c = idx - r * 48;         // 16B chunk
        cp_async16(b_base + (uint32_t)(r * 784 + c * 16), wcc + r * 384 + c * 8);
    }
#pragma unroll
    for (int s = 0; s < 4; s++) {
        const int idx = tid + s * 256;
        const int r = idx >> 3;
        const int c = (idx & 7) * 8;
        cp_async16(a_base + (uint32_t)(r * 144 + c * 2), Abase + (long)r * 384 + c);
    }
    cp_commit();

#pragma unroll 1
    for (int kti = 0; kti < 6; kti++) {
        const int st = kti & 1;
        if (kti + 1 < 6) {
            const int kt = (kti + 1) << 6;
            const uint32_t stoff = (uint32_t)((st ^ 1) * CA_U32 * 4);
#pragma unroll
            for (int s = 0; s < 4; s++) {
                const int idx = tid + s * 256;
                const int r = idx >> 3;
                const int c = (idx & 7) * 8;
                cp_async16(a_base + stoff + (uint32_t)(r * 144 + c * 2),
                           Abase + (long)r * 384 + kt + c);
            }
            cp_commit();
            cp_wait<1>();
        } else {
            cp_wait<0>();
        }
        __syncthreads();

        const uint32_t* Ast = As + st * CA_U32;
        const int kbase = kti * 32;   // u32 offset into full-K B rows

#pragma unroll
        for (int kk2 = 0; kk2 < 32; kk2 += 8) {
            uint32_t af[4], bf[4][2];
            const int row0 = wm + gID;
            af[0] = Ast[row0 * 36 + kk2 + tig];
            af[1] = Ast[(row0 + 8) * 36 + kk2 + tig];
            af[2] = Ast[row0 * 36 + kk2 + tig + 4];
            af[3] = Ast[(row0 + 8) * 36 + kk2 + tig + 4];
#pragma unroll
            for (int nt = 0; nt < 4; nt++) {
                const int col0 = nt * 8 + gID;
                bf[nt][0] = Bs[col0 * 196 + kbase + kk2 + tig];
                bf[nt][1] = Bs[col0 * 196 + kbase + kk2 + tig + 4];
            }
#pragma unroll
            for (int nt = 0; nt < 4; nt++)
                mma_f16(acc[nt], af, bf[nt]);
        }
        __syncthreads();
    }

    // scatter epilogue: rows (wm+gID) and (wm+gID+8); cols o = nt*8 + tig*2
    const long tA = rowBase + wm + gID;
    const long tB = tA + 8;
    const int bA = (int)(tA >> 10), hrA = (int)((tA >> 5) & 31), wcA = (int)(tA & 31);
    const int bB = (int)(tB >> 10), hrB = (int)((tB >> 5) & 31), wcB = (int)(tB & 31);

#pragma unroll
    for (int nt = 0; nt < 4; nt++) {
        const int o = nt * 8 + tig * 2;       // even, 0..30
        if (o < 16) {
            const float b0 = bcH[o], b1 = bcH[o + 1];
            const int hidx = o >> 1;
            *(uint32_t*)&vh[(((long)bA * 32 + wcA) * 8 + hidx) * 64 + hrA * 2] =
                pack_h2(acc[nt][0] + b0, acc[nt][1] + b1);
            *(uint32_t*)&vh[(((long)bB * 32 + wcB) * 8 + hidx) * 64 + hrB * 2] =
                pack_h2(acc[nt][2] + b0, acc[nt][3] + b1);
        } else {
            const int ow = o - 16;
            const float b0 = bcW[ow], b1 = bcW[ow + 1];
            const int hidx = ow >> 1;
            *(uint32_t*)&vw[(((long)bA * 32 + hrA) * 8 + hidx) * 64 + wcA * 2] =
                pack_h2(acc[nt][0] + b0, acc[nt][1] + b1);
            *(uint32_t*)&vw[(((long)bB * 32 + hrB) * 8 + hidx) * 64 + wcB * 2] =
                pack_h2(acc[nt][2] + b0, acc[nt][3] + b1);
        }
    }
}

// ===========================================================================
// Softmax + apply per sequence; stages x from half; outputs f16.
// ===========================================================================
#define MA_SMEM_BYTES ((9216 + 12288) * 4)
#define SMW(h, l, j) smw[(h) * 1152 + (l) * 36 + (j)]

__global__ __launch_bounds__(256) void mixapply_kernel(
    const __half* __restrict__ xh,
    const float* __restrict__ logits,
    __half* __restrict__ out,
    int dir)
{
    extern __shared__ float sm[];
    float* smw = sm;            // [8][32][36]
    float* xs  = sm + 9216;     // [32][384]

    const int n = blockIdx.x;
    const int b = n >> 5;
    const int q = n & 31;
    long base;
    int stride;
    if (dir == 0) { base = ((long)b * 1024 + q) * 384; stride = 32 * 384; }
    else          { base = ((long)(b * 32 + q)) * 32 * 384; stride = 384; }

    const int tid = threadIdx.x;

    for (int i = tid; i < 3072; i += 256) {
        const int r = i / 96;
        const int c4 = i - r * 96;
        uint2 u = *(const uint2*)&xh[base + (long)r * stride + c4 * 4];
        __half2 h0 = *(__half2*)&u.x;
        __half2 h1 = *(__half2*)&u.y;
        float2 f0 = __half22float2(h0);
        float2 f1 = __half22float2(h1);
        *(float4*)&xs[r * 384 + c4 * 4] = make_float4(f0.x, f0.y, f1.x, f1.y);
    }
    const float4* lg = (const float4*)&logits[(long)n * 8192];
    for (int i = tid; i < 2048; i += 256) {
        const int h = i >> 8;
        const int m4 = i & 255;
        const int l = m4 >> 3;
        const int j = (m4 & 7) * 4;
        *(float4*)&SMW(h, l, j) = lg[i];
    }
    __syncthreads();

    {
        const int h = tid >> 5;
        const int j = tid & 31;
        float mx = -1e30f;
#pragma unroll
        for (int l = 0; l < 32; l++) mx = fmaxf(mx, SMW(h, l, j));
        float sum = 0.f;
#pragma unroll
        for (int l = 0; l < 32; l++) {
            float e = __expf(SMW(h, l, j) - mx);
            SMW(h, l, j) = e;
            sum += e;
        }
        float inv = 1.f / sum;
#pragma unroll
        for (int l = 0; l < 32; l++) SMW(h, l, j) *= inv;
    }
    __syncthreads();

    for (int it = tid; it < 768; it += 256) {
        const int jb = it / 96;
        const int c4 = it - jb * 96;
        const int h  = c4 / 12;
        const int j0 = jb * 4;
        float4 a0 = make_float4(0.f, 0.f, 0.f, 0.f);
        float4 a1 = a0, a2 = a0, a3 = a0;
#pragma unroll
        for (int l = 0; l < 32; l++) {
            const float4 xv = *(const float4*)&xs[l * 384 + c4 * 4];
            const float4 wv = *(const float4*)&SMW(h, l, j0);
            a0.x += xv.x * wv.x; a0.y += xv.y * wv.x;
            a0.z += xv.z * wv.x; a0.w += xv.w * wv.x;
            a1.x += xv.x * wv.y; a1.y += xv.y * wv.y;
            a1.z += xv.z * wv.y; a1.w += xv.w * wv.y;
            a2.x += xv.x * wv.z; a2.y += xv.y * wv.z;
            a2.z += xv.z * wv.z; a2.w += xv.w * wv.z;
            a3.x += xv.x * wv.w; a3.y += xv.y * wv.w;
            a3.z += xv.z * wv.w; a3.w += xv.w * wv.w;
        }
        uint2 u0, u1, u2, u3;
        u0.x = pack_h2(a0.x, a0.y); u0.y = pack_h2(a0.z, a0.w);
        u1.x = pack_h2(a1.x, a1.y); u1.y = pack_h2(a1.z, a1.w);
        u2.x = pack_h2(a2.x, a2.y); u2.y = pack_h2(a2.z, a2.w);
        u3.x = pack_h2(a3.x, a3.y); u3.y = pack_h2(a3.z, a3.w);
        *(uint2*)&out[base + (long)(j0 + 0) * stride + c4 * 4] = u0;
        *(uint2*)&out[base + (long)(j0 + 1) * stride + c4 * 4] = u1;
        *(uint2*)&out[base + (long)(j0 + 2) * stride + c4 * 4] = u2;
        *(uint2*)&out[base + (long)(j0 + 3) * stride + c4 * 4] = u3;
    }
}
#undef SMW

// ===========================================================================
// Pool stage 1 (half inputs)
// ===========================================================================
__global__ __launch_bounds__(384) void pool1_kernel(
    const __half* __restrict__ h,
    const __half* __restrict__ w,
    const __half* __restrict__ c,
    float* __restrict__ part)
{
    const int b = blockIdx.x;
    const int ch = blockIdx.y;
    const int t = threadIdx.x;
    long base = ((long)b * 1024 + ch * 64) * 384 + t;
    float s = 0.f;
#pragma unroll 8
    for (int p = 0; p < 64; p++) {
        long o = base + (long)p * 384;
        s += __half2float(h[o]) + __half2float(w[o]) + __half2float(c[o]);
    }
    part[(b * 16 + ch) * 384 + t] = s;
}

// ===========================================================================
// Reweighting MLP + 3-way softmax
// ===========================================================================
__global__ __launch_bounds__(384) void mlp_kernel(
    const float* __restrict__ part,
    const float* __restrict__ Wr1, const float* __restrict__ br1,
    const float* __restrict__ Wr2, const float* __restrict__ br2,
    float* __restrict__ ga)
{
    __shared__ float pool_s[384];
    __shared__ float a1_s[96];
    const int b = blockIdx.x;
    const int t = threadIdx.x;

    float s = 0.f;
#pragma unroll
    for (int ch = 0; ch < 16; ch++) s += part[(b * 16 + ch) * 384 + t];
    pool_s[t] = s * (1.f / 1024.f);
    __syncthreads();

    if (t < 96) {
        float acc = br1[t];
        const float* wr = &Wr1[t * 384];
#pragma unroll 8
        for (int c = 0; c < 384; c++) acc += pool_s[c] * wr[c];
        a1_s[t] = 0.5f * acc * (1.f + erff(acc * 0.70710678118654752f));
    }
    __syncthreads();

    float v[3];
#pragma unroll
    for (int k = 0; k < 3; k++) {
        const int o = t * 3 + k;
        float acc = br2[o];
        const float* wr = &Wr2[o * 96];
#pragma unroll 8
        for (int i = 0; i < 96; i++) acc += a1_s[i] * wr[i];
        v[k] = acc;
    }
    float mx = fmaxf(v[0], fmaxf(v[1], v[2]));
    float e0 = __expf(v[0] - mx);
    float e1 = __expf(v[1] - mx);
    float e2 = __expf(v[2] - mx);
    float inv = 1.f / (e0 + e1 + e2);
    ga[(0 * 64 + b) * 384 + t] = e0 * inv;
    ga[(1 * 64 + b) * 384 + t] = e1 * inv;
    ga[(2 * 64 + b) * 384 + t] = e2 * inv;
}

// ===========================================================================
// Blend (half inputs/output)
// ===========================================================================
__global__ __launch_bounds__(256) void blend_kernel(
    const __half* __restrict__ h,
    const __half* __restrict__ w,
    const __half* __restrict__ c,
    const float* __restrict__ ga,
    __half* __restrict__ cb)
{
    const long i4 = (long)blockIdx.x * blockDim.x + threadIdx.x;
    if (i4 >= (NTOK / 4)) return;
    const long e = i4 * 4;
    const int b = (int)(e / (1024 * 384));
    const int ci = (int)(e % 384);

    uint2 hu = *(const uint2*)&h[e];
    uint2 wu = *(const uint2*)&w[e];
    uint2 cu = *(const uint2*)&c[e];
    float2 h0 = __half22float2(*(__half2*)&hu.x);
    float2 h1 = __half22float2(*(__half2*)&hu.y);
    float2 w0 = __half22float2(*(__half2*)&wu.x);
    float2 w1 = __half22float2(*(__half2*)&wu.y);
    float2 c0 = __half22float2(*(__half2*)&cu.x);
    float2 c1 = __half22float2(*(__half2*)&cu.y);
    float4 a0 = *(const float4*)&ga[(0 * 64 + b) * 384 + ci];
    float4 a1 = *(const float4*)&ga[(1 * 64 + b) * 384 + ci];
    float4 a2 = *(const float4*)&ga[(2 * 64 + b) * 384 + ci];
    float rx = h0.x * a0.x + w0.x * a1.x + c0.x * a2.x;
    float ry = h0.y * a0.y + w0.y * a1.y + c0.y * a2.y;
    float rz = h1.x * a0.z + w1.x * a1.z + c1.x * a2.z;
    float rw = h1.y * a0.w + w1.y * a1.w + c1.y * a2.w;
    uint2 u;
    u.x = pack_h2(rx, ry);
    u.y = pack_h2(rz, rw);
    *(uint2*)&cb[e] = u;
}

// ===========================================================================
// Launch
// ===========================================================================
extern "C" void kernel_launch(void* const* d_in, const int* in_sizes, int n_in,
                              void* d_out, int out_size)
{
    const float* x     = (const float*)d_in[0];
    const float* Wc_h  = (const float*)d_in[1];
    const float* bc_h  = (const float*)d_in[2];
    const float* Wg_h  = (const float*)d_in[3];
    const float* bg_h  = (const float*)d_in[4];
    const float* Wo_h  = (const float*)d_in[5];
    const float* bo_h  = (const float*)d_in[6];
    const float* Wc_w  = (const float*)d_in[7];
    const float* bc_w  = (const float*)d_in[8];
    const float* Wg_w  = (const float*)d_in[9];
    const float* bg_w  = (const float*)d_in[10];
    const float* Wo_w  = (const float*)d_in[11];
    const float* bo_w  = (const float*)d_in[12];
    const float* Wmlpc = (const float*)d_in[13];
    const float* Wr1   = (const float*)d_in[14];
    const float* br1   = (const float*)d_in[15];
    const float* Wr2   = (const float*)d_in[16];
    const float* br2   = (const float*)d_in[17];
    const float* Wp    = (const float*)d_in[18];
    const float* bp    = (const float*)d_in[19];
    float* out = (float*)d_out;

    float *p_part, *p_a, *p_lg;
    __half *p_xh, *p_midh, *p_cbh, *p_hh, *p_wwh, *p_cch;
    __half *p_vhh, *p_vwh, *p_whr, *p_wgh, *p_wcc;
    cudaGetSymbolAddress((void**)&p_part, g_part);
    cudaGetSymbolAddress((void**)&p_a,    g_a);
    cudaGetSymbolAddress((void**)&p_lg,   g_logits);
    cudaGetSymbolAddress((void**)&p_xh,   g_xh);
    cudaGetSymbolAddress((void**)&p_midh, g_midh);
    cudaGetSymbolAddress((void**)&p_cbh,  g_cbh);
    cudaGetSymbolAddress((void**)&p_hh,   g_hh);
    cudaGetSymbolAddress((void**)&p_wwh,  g_wwh);
    cudaGetSymbolAddress((void**)&p_cch,  g_cch);
    cudaGetSymbolAddress((void**)&p_vhh,  g_vhh);
    cudaGetSymbolAddress((void**)&p_vwh,  g_vwh);
    cudaGetSymbolAddress((void**)&p_whr,  g_whr);
    cudaGetSymbolAddress((void**)&p_wgh,  g_wgh);
    cudaGetSymbolAddress((void**)&p_wcc,  g_wcc);

    cudaFuncSetAttribute(gemm_h<float>,
                         cudaFuncAttributeMaxDynamicSharedMemorySize, GEMM_SMEM_BYTES);
    cudaFuncSetAttribute(gemm_h<__half>,
                         cudaFuncAttributeMaxDynamicSharedMemorySize, GEMM_SMEM_BYTES);
    cudaFuncSetAttribute(compress_mma,
                         cudaFuncAttributeMaxDynamicSharedMemorySize, CMP_SMEM_BYTES);
    cudaFuncSetAttribute(mixapply_kernel,
                         cudaFuncAttributeMaxDynamicSharedMemorySize, MA_SMEM_BYTES);

    dim3 ggemm(3, NROWS / 128);
    dim3 ggen(8, 128);

    // one-time weight conversion + x conversion
    round4h_kernel<<<dim3(144, 4), 256>>>(Wo_h, Wo_w, Wp, Wmlpc, p_whr);
    round2h_kernel<<<dim3(64, 2), 256>>>(Wg_h, Wg_w, p_wgh);
    roundwc_kernel<<<12, 256>>>(Wc_h, Wc_w, p_wcc);
    f2h_kernel<<<NTOK / 8 / 256, 256>>>(x, p_xh);

    // compress (MMA, both directions)
    compress_mma<<<NROWS / 128, 256, CMP_SMEM_BYTES>>>(
        p_xh, p_wcc, bc_h, bc_w, p_vhh, p_vwh);

    // H-direction
    gemm_h<float><<<ggen, 256, GEMM_SMEM_BYTES>>>(p_vhh, 64, p_wgh, 64, bg_h, p_lg, 1024, 64);
    mixapply_kernel<<<2048, 256, MA_SMEM_BYTES>>>(p_xh, p_lg, p_midh, 0);
    gemm_h<__half><<<ggemm, 256, GEMM_SMEM_BYTES>>>(p_midh, 384, p_whr, 384, bo_h, p_hh, 384, 384);

    // W-direction
    gemm_h<float><<<ggen, 256, GEMM_SMEM_BYTES>>>(p_vwh, 64, p_wgh + 65536, 64, bg_w, p_lg, 1024, 64);
    mixapply_kernel<<<2048, 256, MA_SMEM_BYTES>>>(p_xh, p_lg, p_midh, 1);
    gemm_h<__half><<<ggemm, 256, GEMM_SMEM_BYTES>>>(p_midh, 384, p_whr + 147456, 384, bo_w, p_wwh, 384, 384);

    // channel path
    gemm_h<__half><<<ggemm, 256, GEMM_SMEM_BYTES>>>(p_xh, 384, p_whr + 3 * 147456, 384, nullptr, p_cch, 384, 384);

    // pool + MLP + blend
    pool1_kernel<<<dim3(64, 16), 384>>>(p_hh, p_wwh, p_cch, p_part);
    mlp_kernel<<<64, 384>>>(p_part, Wr1, br1, Wr2, br2, p_a);
    blend_kernel<<<(NTOK / 4 + 255) / 256, 256>>>(p_hh, p_wwh, p_cch, p_a, p_cbh);

    // final projection
    gemm_h<float><<<ggemm, 256, GEMM_SMEM_BYTES>>>(p_cbh, 384, p_whr + 2 * 147456, 384, bp, out, 384, 384);
}